// round 6
// baseline (speedup 1.0000x reference)
#include <cuda_runtime.h>
#include <cuda_bf16.h>

#define NNODE 100000
#define EMAX  1600000
#define CDIM 64

__device__ __align__(16) float g_h[NNODE * CDIM];
__device__ __align__(16) float g_PA[NNODE * CDIM];
__device__ __align__(16) float g_PB[NNODE * CDIM];
__device__ __align__(16) float g_pd[EMAX * 4];        // pos_diff (edge order)
__device__ __align__(16) float g_epd[EMAX * 4];       // pos_diff (dst-sorted order)
__device__ int   g_src[EMAX];
__device__ int   g_dst[EMAX];
__device__ int   g_esrc[EMAX];                        // src, dst-sorted order
__device__ int   g_deg[NNODE];
__device__ int   g_start[NNODE];                      // exclusive prefix of deg
__device__ int   g_cursor[NNODE];
__device__ int   g_bsum[512];
__device__ int   g_boff[512];
__device__ int   g_mode;                              // 1 = int64 indices, 0 = int32

__device__ __forceinline__ float elu_f(float v) {
    return v > 0.f ? v : expm1f(v);
}

// packed fp32x2 helpers (sm_100+)
__device__ __forceinline__ void ffma2(unsigned long long& d, unsigned long long a, unsigned long long b) {
    asm("fma.rn.f32x2 %0, %1, %2, %0;" : "+l"(d) : "l"(a), "l"(b));
}
__device__ __forceinline__ float usum(unsigned long long v) {
    float lo, hi;
    asm("mov.b64 {%0,%1}, %2;" : "=f"(lo), "=f"(hi) : "l"(v));
    return lo + hi;
}

// ------------------------------------------------------------------ probe index dtype
__global__ void probe_kernel(const int* __restrict__ w) {
    if (threadIdx.x == 0 && blockIdx.x == 0) {
        bool all_odd_zero = true;
        for (int i = 1; i < 64; i += 2)
            if (w[i] != 0) { all_odd_zero = false; break; }
        g_mode = all_odd_zero ? 1 : 0;
    }
}

__global__ void zero_deg_kernel(int Nn) {
    for (int i = blockIdx.x * blockDim.x + threadIdx.x; i < Nn; i += gridDim.x * blockDim.x)
        g_deg[i] = 0;
}

// ------------------------------------------------------------------ convert indices + pos_diff + degree
__global__ void convert_kernel(const int* __restrict__ w, const float* __restrict__ pos, int Ecnt) {
    int mode = g_mode;
    for (int e = blockIdx.x * blockDim.x + threadIdx.x; e < Ecnt; e += gridDim.x * blockDim.x) {
        int s, d;
        if (mode) { s = w[2 * e]; d = w[2 * (Ecnt + e)]; }
        else      { s = w[e];     d = w[Ecnt + e]; }
        s = min(max(s, 0), NNODE - 1);
        d = min(max(d, 0), NNODE - 1);
        g_src[e] = s;
        g_dst[e] = d;
        atomicAdd(&g_deg[d], 1);
        float4 pd;
        pd.x = pos[s * 3 + 0] - pos[d * 3 + 0];
        pd.y = pos[s * 3 + 1] - pos[d * 3 + 1];
        pd.z = pos[s * 3 + 2] - pos[d * 3 + 2];
        pd.w = 0.f;
        reinterpret_cast<float4*>(g_pd)[e] = pd;
    }
}

// ------------------------------------------------------------------ 3-pass exclusive scan of g_deg
__global__ void scan_sum_kernel(int Nn) {
    __shared__ int sred[256];
    int i = blockIdx.x * 256 + threadIdx.x;
    int v = (i < Nn) ? g_deg[i] : 0;
    sred[threadIdx.x] = v;
    __syncthreads();
    for (int off = 128; off; off >>= 1) {
        if (threadIdx.x < off) sred[threadIdx.x] += sred[threadIdx.x + off];
        __syncthreads();
    }
    if (threadIdx.x == 0) g_bsum[blockIdx.x] = sred[0];
}
__global__ void scan_top_kernel(int nb) {
    __shared__ int s[512];
    int tid = threadIdx.x;
    int v = (tid < nb) ? g_bsum[tid] : 0;
    s[tid] = v;
    __syncthreads();
    for (int off = 1; off < 512; off <<= 1) {
        int t = (tid >= off) ? s[tid - off] : 0;
        __syncthreads();
        s[tid] += t;
        __syncthreads();
    }
    g_boff[tid] = s[tid] - v;   // exclusive
}
__global__ void scan_apply_kernel(int Nn) {
    __shared__ int s[256];
    int i = blockIdx.x * 256 + threadIdx.x;
    int v = (i < Nn) ? g_deg[i] : 0;
    s[threadIdx.x] = v;
    __syncthreads();
    for (int off = 1; off < 256; off <<= 1) {
        int t = (threadIdx.x >= off) ? s[threadIdx.x - off] : 0;
        __syncthreads();
        s[threadIdx.x] += t;
        __syncthreads();
    }
    if (i < Nn) {
        int ex = g_boff[blockIdx.x] + s[threadIdx.x] - v;
        g_cursor[i] = ex;
        g_start[i]  = ex;
    }
}

// ------------------------------------------------------------------ bin edges by dst (counting sort scatter)
__global__ void binplace_kernel(int Ecnt) {
    for (int e = blockIdx.x * blockDim.x + threadIdx.x; e < Ecnt; e += gridDim.x * blockDim.x) {
        int d = g_dst[e];
        int p = atomicAdd(&g_cursor[d], 1);
        g_esrc[p] = g_src[e];
        reinterpret_cast<float4*>(g_epd)[p] = reinterpret_cast<const float4*>(g_pd)[e];
    }
}

// ------------------------------------------------------------------ encoder (f32x2)
__global__ void encoder_kernel(const float* __restrict__ x,
                               const float* __restrict__ W0, const float* __restrict__ b0,
                               const float* __restrict__ W1, const float* __restrict__ b1,
                               int Nn) {
    extern __shared__ float sm[];
    float* sW1 = sm;            // 4096, kpair-packed
    float* sW0 = sm + 4096;     // 192
    float* sb0 = sm + 4288;     // 64
    float* sb1 = sm + 4352;     // 64
    float* stage = sm + 4416;   // 8 warps * 320

    for (int t = threadIdx.x; t < 4096; t += blockDim.x) {
        int c = t & 3, lane_ = (t >> 2) & 31, kp = t >> 7;
        int k = 2 * kp + (c & 1);
        int col = lane_ + ((c & 2) ? 32 : 0);
        sW1[t] = W1[k * 64 + col];
    }
    for (int t = threadIdx.x; t < 192; t += blockDim.x) sW0[t] = W0[t];
    if (threadIdx.x < 64) { sb0[threadIdx.x] = b0[threadIdx.x]; sb1[threadIdx.x] = b1[threadIdx.x]; }
    __syncthreads();

    int lane = threadIdx.x & 31;
    int wid  = threadIdx.x >> 5;
    float* wbase = stage + wid * 320;
    const ulonglong2* W1v = reinterpret_cast<const ulonglong2*>(sW1);
    const unsigned long long* nU = reinterpret_cast<const unsigned long long*>(wbase);
    float* hF = wbase;

    int wg = blockIdx.x * (blockDim.x >> 5) + wid;
    int ws = gridDim.x * (blockDim.x >> 5);
    for (int base = wg * 4; base < Nn; base += ws * 4) {
        int rL = ((lane >> 1) * 5) * 2 + (lane & 1);
        int rH = ((16 + (lane >> 1)) * 5) * 2 + (lane & 1);
#pragma unroll
        for (int i = 0; i < 4; i++) {
            int n = base + i;
            float h0 = 0.f, h1 = 0.f;
            if (n < Nn) {
                float x0 = __ldg(&x[n * 3 + 0]), x1 = __ldg(&x[n * 3 + 1]), x2 = __ldg(&x[n * 3 + 2]);
                h0 = elu_f(x0 * sW0[lane]      + x1 * sW0[64 + lane]      + x2 * sW0[128 + lane]      + sb0[lane]);
                h1 = elu_f(x0 * sW0[lane + 32] + x1 * sW0[64 + lane + 32] + x2 * sW0[128 + lane + 32] + sb0[lane + 32]);
            }
            hF[rL + 2 * i] = h0;
            hF[rH + 2 * i] = h1;
        }
        __syncwarp();

        unsigned long long a0[4] = {0,0,0,0}, a1[4] = {0,0,0,0};
#pragma unroll 4
        for (int kp = 0; kp < 32; kp++) {
            ulonglong2 w = W1v[kp * 32 + lane];
#pragma unroll
            for (int i = 0; i < 4; i++) {
                unsigned long long v = nU[kp * 5 + i];
                ffma2(a0[i], v, w.x); ffma2(a1[i], v, w.y);
            }
        }
        float b1a = sb1[lane], b1b = sb1[lane + 32];
#pragma unroll
        for (int i = 0; i < 4; i++) {
            int n = base + i;
            if (n < Nn) {
                g_h[n * 64 + lane]      = usum(a0[i]) + b1a;
                g_h[n * 64 + 32 + lane] = usum(a1[i]) + b1b;
            }
        }
        __syncwarp();
    }
}

// ------------------------------------------------------------------ per-layer precompute:
// PA[n] = h[n]·(W0a+W0c),  PB[n] = h[n]·(W0b−W0c) + b0
__global__ void precompute_kernel(const float* __restrict__ E0, const float* __restrict__ eb0, int Nn) {
    extern __shared__ float sm[];
    float* sWA = sm;            // 4096
    float* sWB = sm + 4096;     // 4096
    float* sb0 = sm + 8192;     // 64
    float* stage = sm + 8256;   // 8 warps * 320 floats

    for (int t = threadIdx.x; t < 4096; t += blockDim.x) {
        int c = t & 3, lane_ = (t >> 2) & 31, kp = t >> 7;
        int k = 2 * kp + (c & 1);
        int col = lane_ + ((c & 2) ? 32 : 0);
        float wC = E0[(128 + k) * 64 + col];
        sWA[t] = E0[k * 64 + col] + wC;
        sWB[t] = E0[(64 + k) * 64 + col] - wC;
    }
    if (threadIdx.x < 64) sb0[threadIdx.x] = eb0[threadIdx.x];
    __syncthreads();

    int lane = threadIdx.x & 31;
    int wid  = threadIdx.x >> 5;
    float* wbase = stage + wid * 320;
    float2* nP = reinterpret_cast<float2*>(wbase);
    const ulonglong2* WAv = reinterpret_cast<const ulonglong2*>(sWA);
    const ulonglong2* WBv = reinterpret_cast<const ulonglong2*>(sWB);
    const unsigned long long* nU = reinterpret_cast<const unsigned long long*>(nP);

    int wg = blockIdx.x * (blockDim.x >> 5) + wid;
    int ws = gridDim.x * (blockDim.x >> 5);
    for (int base = wg * 4; base < Nn; base += ws * 4) {
#pragma unroll
        for (int i = 0; i < 4; i++) {
            int n = base + i;
            nP[lane * 5 + i] = (n < Nn) ? reinterpret_cast<const float2*>(g_h + n * 64)[lane]
                                        : make_float2(0.f, 0.f);
        }
        __syncwarp();

        unsigned long long aA0[4] = {0,0,0,0}, aA1[4] = {0,0,0,0};
        unsigned long long aB0[4] = {0,0,0,0}, aB1[4] = {0,0,0,0};
#pragma unroll 4
        for (int kp = 0; kp < 32; kp++) {
            ulonglong2 wa = WAv[kp * 32 + lane];
            ulonglong2 wb = WBv[kp * 32 + lane];
#pragma unroll
            for (int i = 0; i < 4; i++) {
                unsigned long long v = nU[kp * 5 + i];
                ffma2(aA0[i], v, wa.x); ffma2(aA1[i], v, wa.y);
                ffma2(aB0[i], v, wb.x); ffma2(aB1[i], v, wb.y);
            }
        }
        float b0a = sb0[lane], b0b = sb0[lane + 32];
#pragma unroll
        for (int i = 0; i < 4; i++) {
            int n = base + i;
            if (n < Nn) {
                g_PA[n * 64 + lane]      = usum(aA0[i]);
                g_PA[n * 64 + 32 + lane] = usum(aA1[i]);
                g_PB[n * 64 + lane]      = usum(aB0[i]) + b0a;
                g_PB[n * 64 + 32 + lane] = usum(aB1[i]) + b0b;
            }
        }
        __syncwarp();
    }
}

// ------------------------------------------------------------------ fused MP layer:
// For 4 owned nodes per warp:
//   Hsum[n] = sum over edges e with dst=n of elu(PA[src_e] + PB[n] + pd_e·Wp)   (registers!)
//   agg = Hsum·eW1 + deg·eb1
//   u   = elu([h, agg]·nW0 + nb0)·nW1 + nb1 ;  h += u
__global__ void mp_layer_kernel(const float* __restrict__ E1, const float* __restrict__ eb1,
                                const float* __restrict__ W0, const float* __restrict__ b0,
                                const float* __restrict__ W1, const float* __restrict__ b1,
                                const float* __restrict__ Wp, int Nn) {
    extern __shared__ float sm[];
    float* sE1 = sm;                 // 4096
    float* sW0 = sm + 4096;          // 8192
    float* sW1 = sm + 12288;         // 4096
    float* seb1 = sm + 16384;        // 64
    float* snb0 = sm + 16448;        // 64
    float* snb1 = sm + 16512;        // 64
    float* stage = sm + 16576;       // 8 warps * 640

    for (int t = threadIdx.x; t < 4096; t += blockDim.x) {
        int c = t & 3, lane_ = (t >> 2) & 31, kp = t >> 7;
        int k = 2 * kp + (c & 1);
        int col = lane_ + ((c & 2) ? 32 : 0);
        sE1[t] = E1[k * 64 + col];
        sW1[t] = W1[k * 64 + col];
    }
    for (int t = threadIdx.x; t < 8192; t += blockDim.x) {
        int c = t & 3, lane_ = (t >> 2) & 31, kp = t >> 7;
        int k = 2 * kp + (c & 1);
        int col = lane_ + ((c & 2) ? 32 : 0);
        sW0[t] = W0[k * 64 + col];
    }
    if (threadIdx.x < 64) {
        seb1[threadIdx.x] = eb1[threadIdx.x];
        snb0[threadIdx.x] = b0[threadIdx.x];
        snb1[threadIdx.x] = b1[threadIdx.x];
    }
    __syncthreads();

    int lane = threadIdx.x & 31;
    int wid  = threadIdx.x >> 5;
    float* wbase = stage + wid * 640;
    float2* nP = reinterpret_cast<float2*>(wbase);   // kpairs 0..31 = h (→hidden), 32..63 = Hsum (→agg)
    const ulonglong2* E1v = reinterpret_cast<const ulonglong2*>(sE1);
    const ulonglong2* W0v = reinterpret_cast<const ulonglong2*>(sW0);
    const ulonglong2* W1v = reinterpret_cast<const ulonglong2*>(sW1);
    const unsigned long long* nU = reinterpret_cast<const unsigned long long*>(nP);
    float* hF = wbase;

    float2 wp0 = __ldg(&reinterpret_cast<const float2*>(Wp)[lane]);
    float2 wp1 = __ldg(&reinterpret_cast<const float2*>(Wp + 64)[lane]);
    float2 wp2 = __ldg(&reinterpret_cast<const float2*>(Wp + 128)[lane]);

    const float4* epd4 = reinterpret_cast<const float4*>(g_epd);
    const float2* PA2  = reinterpret_cast<const float2*>(g_PA);
    const float2* PB2  = reinterpret_cast<const float2*>(g_PB);
    const float2* H2   = reinterpret_cast<const float2*>(g_h);

    int wg = blockIdx.x * (blockDim.x >> 5) + wid;
    int ws = gridDim.x * (blockDim.x >> 5);
    for (int base = wg * 4; base < Nn; base += ws * 4) {
        int st[4], en[4];
        float degf[4], pbx[4], pby[4];
#pragma unroll
        for (int i = 0; i < 4; i++) {
            int n = base + i;
            bool v = (n < Nn);
            int dg = v ? __ldg(&g_deg[n]) : 0;
            st[i] = v ? __ldg(&g_start[n]) : 0;
            en[i] = st[i] + dg;
            degf[i] = (float)dg;
            if (v) {
                float2 pb = __ldg(&PB2[(size_t)n * 32 + lane]);
                pbx[i] = pb.x; pby[i] = pb.y;
                nP[lane * 5 + i] = __ldg(&H2[(size_t)n * 32 + lane]);
            } else {
                pbx[i] = 0.f; pby[i] = 0.f;
                nP[lane * 5 + i] = make_float2(0.f, 0.f);
            }
        }

        // ---- edge accumulation in registers (src prefetched 1 step ahead)
        float ax[4] = {0.f, 0.f, 0.f, 0.f}, ay[4] = {0.f, 0.f, 0.f, 0.f};
        int maxd = max(max(en[0] - st[0], en[1] - st[1]), max(en[2] - st[2], en[3] - st[3]));
        int svn[4];
#pragma unroll
        for (int i = 0; i < 4; i++)
            svn[i] = (st[i] < en[i]) ? __ldg(&g_esrc[st[i]]) : 0;
        for (int t = 0; t < maxd; t++) {
            int svc[4];
#pragma unroll
            for (int i = 0; i < 4; i++) svc[i] = svn[i];
#pragma unroll
            for (int i = 0; i < 4; i++) {
                int e = st[i] + t + 1;
                svn[i] = (e < en[i]) ? __ldg(&g_esrc[e]) : 0;
            }
#pragma unroll
            for (int i = 0; i < 4; i++) {
                int e = st[i] + t;
                if (e < en[i]) {
                    float4 pd = __ldg(&epd4[e]);
                    float2 pa = __ldg(&PA2[(size_t)svc[i] * 32 + lane]);
                    float hx = elu_f(pa.x + pbx[i] + pd.x * wp0.x + pd.y * wp1.x + pd.z * wp2.x);
                    float hy = elu_f(pa.y + pby[i] + pd.x * wp0.y + pd.y * wp1.y + pd.z * wp2.y);
                    ax[i] += hx; ay[i] += hy;
                }
            }
        }
        __syncwarp();
#pragma unroll
        for (int i = 0; i < 4; i++)
            nP[(32 + lane) * 5 + i] = make_float2(ax[i], ay[i]);
        __syncwarp();

        // ---- GEMM1: agg = Hsum·E1 + deg·eb1
        unsigned long long a0[4] = {0,0,0,0}, a1[4] = {0,0,0,0};
#pragma unroll 4
        for (int kp = 0; kp < 32; kp++) {
            ulonglong2 w = E1v[kp * 32 + lane];
#pragma unroll
            for (int i = 0; i < 4; i++) {
                unsigned long long v = nU[(32 + kp) * 5 + i];
                ffma2(a0[i], v, w.x); ffma2(a1[i], v, w.y);
            }
        }
        float e1a = seb1[lane], e1b = seb1[lane + 32];
        float aggL[4], aggH[4];
#pragma unroll
        for (int i = 0; i < 4; i++) {
            aggL[i] = usum(a0[i]) + degf[i] * e1a;
            aggH[i] = usum(a1[i]) + degf[i] * e1b;
        }
        __syncwarp();
        {
            int rL = ((32 + (lane >> 1)) * 5) * 2 + (lane & 1);
            int rH = ((48 + (lane >> 1)) * 5) * 2 + (lane & 1);
#pragma unroll
            for (int i = 0; i < 4; i++) {
                hF[rL + 2 * i] = aggL[i];
                hF[rH + 2 * i] = aggH[i];
            }
        }
        __syncwarp();

        // ---- GEMM2: hidden = elu([h, agg]·W0 + b0)
        unsigned long long c0[4] = {0,0,0,0}, c1[4] = {0,0,0,0};
#pragma unroll 4
        for (int kp = 0; kp < 64; kp++) {
            ulonglong2 w = W0v[kp * 32 + lane];
#pragma unroll
            for (int i = 0; i < 4; i++) {
                unsigned long long v = nU[kp * 5 + i];
                ffma2(c0[i], v, w.x); ffma2(c1[i], v, w.y);
            }
        }
        float b0a = snb0[lane], b0b = snb0[lane + 32];
        float hL[4], hH[4];
#pragma unroll
        for (int i = 0; i < 4; i++) {
            hL[i] = elu_f(usum(c0[i]) + b0a);
            hH[i] = elu_f(usum(c1[i]) + b0b);
        }
        __syncwarp();
        {
            int rL = ((lane >> 1) * 5) * 2 + (lane & 1);
            int rH = ((16 + (lane >> 1)) * 5) * 2 + (lane & 1);
#pragma unroll
            for (int i = 0; i < 4; i++) {
                hF[rL + 2 * i] = hL[i];
                hF[rH + 2 * i] = hH[i];
            }
        }
        __syncwarp();

        // ---- GEMM3: u = hidden·W1 + b1 ; h += u
        unsigned long long d0[4] = {0,0,0,0}, d1[4] = {0,0,0,0};
#pragma unroll 4
        for (int kp = 0; kp < 32; kp++) {
            ulonglong2 w = W1v[kp * 32 + lane];
#pragma unroll
            for (int i = 0; i < 4; i++) {
                unsigned long long v = nU[kp * 5 + i];
                ffma2(d0[i], v, w.x); ffma2(d1[i], v, w.y);
            }
        }
        float b1a = snb1[lane], b1b = snb1[lane + 32];
#pragma unroll
        for (int i = 0; i < 4; i++) {
            int n = base + i;
            if (n < Nn) {
                float old0 = g_h[n * 64 + lane];
                float old1 = g_h[n * 64 + 32 + lane];
                g_h[n * 64 + lane]      = old0 + usum(d0[i]) + b1a;
                g_h[n * 64 + 32 + lane] = old1 + usum(d1[i]) + b1b;
            }
        }
        __syncwarp();
    }
}

// ------------------------------------------------------------------ decoder (f32x2)
__global__ void decoder_kernel(const float* __restrict__ W0, const float* __restrict__ b0,
                               const float* __restrict__ W1, const float* __restrict__ b1,
                               float* __restrict__ out, int Nn) {
    extern __shared__ float sm[];
    float* sW0 = sm;            // 4096, kpair-packed
    float* sW1 = sm + 4096;     // 192 (row-major [64][3])
    float* sb0 = sm + 4288;     // 64
    float* sb1v = sm + 4352;    // 3 (+pad)
    float* stage = sm + 4356;   // 8 warps * 320

    for (int t = threadIdx.x; t < 4096; t += blockDim.x) {
        int c = t & 3, lane_ = (t >> 2) & 31, kp = t >> 7;
        int k = 2 * kp + (c & 1);
        int col = lane_ + ((c & 2) ? 32 : 0);
        sW0[t] = W0[k * 64 + col];
    }
    for (int t = threadIdx.x; t < 192; t += blockDim.x) sW1[t] = W1[t];
    if (threadIdx.x < 64) sb0[threadIdx.x] = b0[threadIdx.x];
    if (threadIdx.x < 3)  sb1v[threadIdx.x] = b1[threadIdx.x];
    __syncthreads();

    int lane = threadIdx.x & 31;
    int wid  = threadIdx.x >> 5;
    float* wbase = stage + wid * 320;
    float2* nP = reinterpret_cast<float2*>(wbase);
    const ulonglong2* W0v = reinterpret_cast<const ulonglong2*>(sW0);
    const unsigned long long* nU = reinterpret_cast<const unsigned long long*>(nP);
    const float2* H2 = reinterpret_cast<const float2*>(g_h);

    int wg = blockIdx.x * (blockDim.x >> 5) + wid;
    int ws = gridDim.x * (blockDim.x >> 5);
    for (int base = wg * 4; base < Nn; base += ws * 4) {
#pragma unroll
        for (int i = 0; i < 4; i++) {
            int n = base + i;
            nP[lane * 5 + i] = (n < Nn) ? __ldg(&H2[(size_t)n * 32 + lane]) : make_float2(0.f, 0.f);
        }
        __syncwarp();

        unsigned long long a0[4] = {0,0,0,0}, a1[4] = {0,0,0,0};
#pragma unroll 4
        for (int kp = 0; kp < 32; kp++) {
            ulonglong2 w = W0v[kp * 32 + lane];
#pragma unroll
            for (int i = 0; i < 4; i++) {
                unsigned long long v = nU[kp * 5 + i];
                ffma2(a0[i], v, w.x); ffma2(a1[i], v, w.y);
            }
        }
        float b0a = sb0[lane], b0b = sb0[lane + 32];
        float w1L0 = sW1[lane * 3 + 0], w1L1 = sW1[lane * 3 + 1], w1L2 = sW1[lane * 3 + 2];
        float w1H0 = sW1[(lane + 32) * 3 + 0], w1H1 = sW1[(lane + 32) * 3 + 1], w1H2 = sW1[(lane + 32) * 3 + 2];
#pragma unroll
        for (int i = 0; i < 4; i++) {
            int n = base + i;
            float hid0 = elu_f(usum(a0[i]) + b0a);
            float hid1 = elu_f(usum(a1[i]) + b0b);
            float p0 = hid0 * w1L0 + hid1 * w1H0;
            float p1 = hid0 * w1L1 + hid1 * w1H1;
            float p2 = hid0 * w1L2 + hid1 * w1H2;
#pragma unroll
            for (int off = 16; off; off >>= 1) {
                p0 += __shfl_xor_sync(~0u, p0, off);
                p1 += __shfl_xor_sync(~0u, p1, off);
                p2 += __shfl_xor_sync(~0u, p2, off);
            }
            if (lane == 0 && n < Nn) {
                out[n * 3 + 0] = p0 + sb1v[0];
                out[n * 3 + 1] = p1 + sb1v[1];
                out[n * 3 + 2] = p2 + sb1v[2];
            }
        }
        __syncwarp();
    }
}

// ------------------------------------------------------------------ launch
extern "C" void kernel_launch(void* const* d_in, const int* in_sizes, int n_in,
                              void* d_out, int out_size) {
    const float* x      = (const float*)d_in[0];
    const float* pos    = (const float*)d_in[1];
    const int*   ei     = (const int*)d_in[2];   // dtype auto-detected on device
    const float* enc_W0 = (const float*)d_in[3];
    const float* enc_b0 = (const float*)d_in[4];
    const float* enc_W1 = (const float*)d_in[5];
    const float* enc_b1 = (const float*)d_in[6];
    const float* dec_W0 = (const float*)d_in[7];
    const float* dec_b0 = (const float*)d_in[8];
    const float* dec_W1 = (const float*)d_in[9];
    const float* dec_b1 = (const float*)d_in[10];
    const float* eW0    = (const float*)d_in[11];
    const float* eb0    = (const float*)d_in[12];
    const float* eW1    = (const float*)d_in[13];
    const float* eb1    = (const float*)d_in[14];
    const float* nW0    = (const float*)d_in[15];
    const float* nb0    = (const float*)d_in[16];
    const float* nW1    = (const float*)d_in[17];
    const float* nb1    = (const float*)d_in[18];

    int Nn   = in_sizes[0] / 3;
    int Ecnt = in_sizes[2] / 2;
    if (Ecnt > EMAX) Ecnt = EMAX;
    float* out = (float*)d_out;

    const int ENC_SMEM  = (4416 + 8 * 320) * 4;    // 27,904 B
    const int PRE_SMEM  = (8256 + 8 * 320) * 4;    // 43,264 B
    const int MPL_SMEM  = (16576 + 8 * 640) * 4;   // 86,784 B
    const int DEC_SMEM  = (4356 + 8 * 320) * 4;    // 27,664 B
    cudaFuncSetAttribute(precompute_kernel, cudaFuncAttributeMaxDynamicSharedMemorySize, PRE_SMEM);
    cudaFuncSetAttribute(mp_layer_kernel,   cudaFuncAttributeMaxDynamicSharedMemorySize, MPL_SMEM);

    const int TPB = 256;
    int nscan = (Nn + 255) / 256;

    probe_kernel<<<1, 32>>>(ei);
    zero_deg_kernel<<<148, TPB>>>(Nn);
    convert_kernel<<<444, TPB>>>(ei, pos, Ecnt);
    scan_sum_kernel<<<nscan, 256>>>(Nn);
    scan_top_kernel<<<1, 512>>>(nscan);
    scan_apply_kernel<<<nscan, 256>>>(Nn);
    binplace_kernel<<<444, TPB>>>(Ecnt);
    encoder_kernel<<<296, TPB, ENC_SMEM>>>(x, enc_W0, enc_b0, enc_W1, enc_b1, Nn);
    for (int l = 0; l < 2; l++) {
        const float* E0l = eW0 + (size_t)l * 195 * 64;
        precompute_kernel<<<296, TPB, PRE_SMEM>>>(E0l, eb0 + l * 64, Nn);
        mp_layer_kernel<<<296, TPB, MPL_SMEM>>>(eW1 + (size_t)l * 64 * 64, eb1 + l * 64,
                                                nW0 + (size_t)l * 128 * 64, nb0 + l * 64,
                                                nW1 + (size_t)l * 64 * 64,  nb1 + l * 64,
                                                E0l + 192 * 64, Nn);
    }
    decoder_kernel<<<296, TPB, DEC_SMEM>>>(dec_W0, dec_b0, dec_W1, dec_b1, out, Nn);
}

// round 7
// speedup vs baseline: 1.1524x; 1.1524x over previous
#include <cuda_runtime.h>
#include <cuda_bf16.h>

#define NNODE 100000
#define EMAX  1600000
#define CDIM 64

__device__ __align__(16) float g_h[NNODE * CDIM];
__device__ __align__(16) float g_agg[NNODE * CDIM];
__device__ __align__(16) float g_PA[NNODE * CDIM];
__device__ __align__(16) float g_PB[NNODE * CDIM];
__device__ __align__(16) float g_pd[EMAX * 4];        // pos_diff, padded float4
__device__ int   g_src[EMAX];
__device__ int   g_dst[EMAX];
__device__ int   g_deg[NNODE];
__device__ int   g_mode;                              // 1 = int64 indices, 0 = int32

__device__ __forceinline__ float elu_f(float v) {
    return v > 0.f ? v : expm1f(v);
}

// packed fp32x2 helpers (sm_100+)
__device__ __forceinline__ void ffma2(unsigned long long& d, unsigned long long a, unsigned long long b) {
    asm("fma.rn.f32x2 %0, %1, %2, %0;" : "+l"(d) : "l"(a), "l"(b));
}
__device__ __forceinline__ float usum(unsigned long long v) {
    float lo, hi;
    asm("mov.b64 {%0,%1}, %2;" : "=f"(lo), "=f"(hi) : "l"(v));
    return lo + hi;
}
// vectorized reduction to global (sm_90+)
__device__ __forceinline__ void red_add_v4(float* addr, float x, float y, float z, float w) {
    asm volatile("red.global.add.v4.f32 [%0], {%1, %2, %3, %4};"
                 :: "l"(addr), "f"(x), "f"(y), "f"(z), "f"(w) : "memory");
}

// ------------------------------------------------------------------ probe index dtype
__global__ void probe_kernel(const int* __restrict__ w) {
    if (threadIdx.x == 0 && blockIdx.x == 0) {
        bool all_odd_zero = true;
        for (int i = 1; i < 64; i += 2)
            if (w[i] != 0) { all_odd_zero = false; break; }
        g_mode = all_odd_zero ? 1 : 0;
    }
}

__global__ void zero_deg_kernel(int Nn) {
    for (int i = blockIdx.x * blockDim.x + threadIdx.x; i < Nn; i += gridDim.x * blockDim.x)
        g_deg[i] = 0;
}
__global__ void zero_agg_kernel(int n4) {
    float4* p = reinterpret_cast<float4*>(g_agg);
    for (int i = blockIdx.x * blockDim.x + threadIdx.x; i < n4; i += gridDim.x * blockDim.x)
        p[i] = make_float4(0.f, 0.f, 0.f, 0.f);
}

// ------------------------------------------------------------------ convert indices + pos_diff + degree
__global__ void convert_kernel(const int* __restrict__ w, const float* __restrict__ pos, int Ecnt) {
    int mode = g_mode;
    for (int e = blockIdx.x * blockDim.x + threadIdx.x; e < Ecnt; e += gridDim.x * blockDim.x) {
        int s, d;
        if (mode) { s = w[2 * e]; d = w[2 * (Ecnt + e)]; }
        else      { s = w[e];     d = w[Ecnt + e]; }
        s = min(max(s, 0), NNODE - 1);
        d = min(max(d, 0), NNODE - 1);
        g_src[e] = s;
        g_dst[e] = d;
        atomicAdd(&g_deg[d], 1);
        float4 pd;
        pd.x = pos[s * 3 + 0] - pos[d * 3 + 0];
        pd.y = pos[s * 3 + 1] - pos[d * 3 + 1];
        pd.z = pos[s * 3 + 2] - pos[d * 3 + 2];
        pd.w = 0.f;
        reinterpret_cast<float4*>(g_pd)[e] = pd;
    }
}

// ------------------------------------------------------------------ encoder (f32x2)
__global__ void encoder_kernel(const float* __restrict__ x,
                               const float* __restrict__ W0, const float* __restrict__ b0,
                               const float* __restrict__ W1, const float* __restrict__ b1,
                               int Nn) {
    extern __shared__ float sm[];
    float* sW1 = sm;            // 4096, kpair-packed
    float* sW0 = sm + 4096;     // 192
    float* sb0 = sm + 4288;     // 64
    float* sb1 = sm + 4352;     // 64
    float* stage = sm + 4416;   // 8 warps * 320

    for (int t = threadIdx.x; t < 4096; t += blockDim.x) {
        int c = t & 3, lane_ = (t >> 2) & 31, kp = t >> 7;
        int k = 2 * kp + (c & 1);
        int col = lane_ + ((c & 2) ? 32 : 0);
        sW1[t] = W1[k * 64 + col];
    }
    for (int t = threadIdx.x; t < 192; t += blockDim.x) sW0[t] = W0[t];
    if (threadIdx.x < 64) { sb0[threadIdx.x] = b0[threadIdx.x]; sb1[threadIdx.x] = b1[threadIdx.x]; }
    __syncthreads();

    int lane = threadIdx.x & 31;
    int wid  = threadIdx.x >> 5;
    float* wbase = stage + wid * 320;
    const ulonglong2* W1v = reinterpret_cast<const ulonglong2*>(sW1);
    const unsigned long long* nU = reinterpret_cast<const unsigned long long*>(wbase);
    float* hF = wbase;

    int wg = blockIdx.x * (blockDim.x >> 5) + wid;
    int ws = gridDim.x * (blockDim.x >> 5);
    for (int base = wg * 4; base < Nn; base += ws * 4) {
        int rL = ((lane >> 1) * 5) * 2 + (lane & 1);
        int rH = ((16 + (lane >> 1)) * 5) * 2 + (lane & 1);
#pragma unroll
        for (int i = 0; i < 4; i++) {
            int n = base + i;
            float h0 = 0.f, h1 = 0.f;
            if (n < Nn) {
                float x0 = __ldg(&x[n * 3 + 0]), x1 = __ldg(&x[n * 3 + 1]), x2 = __ldg(&x[n * 3 + 2]);
                h0 = elu_f(x0 * sW0[lane]      + x1 * sW0[64 + lane]      + x2 * sW0[128 + lane]      + sb0[lane]);
                h1 = elu_f(x0 * sW0[lane + 32] + x1 * sW0[64 + lane + 32] + x2 * sW0[128 + lane + 32] + sb0[lane + 32]);
            }
            hF[rL + 2 * i] = h0;
            hF[rH + 2 * i] = h1;
        }
        __syncwarp();

        unsigned long long a0[4] = {0,0,0,0}, a1[4] = {0,0,0,0};
#pragma unroll 4
        for (int kp = 0; kp < 32; kp++) {
            ulonglong2 w = W1v[kp * 32 + lane];
#pragma unroll
            for (int i = 0; i < 4; i++) {
                unsigned long long v = nU[kp * 5 + i];
                ffma2(a0[i], v, w.x); ffma2(a1[i], v, w.y);
            }
        }
        float b1a = sb1[lane], b1b = sb1[lane + 32];
#pragma unroll
        for (int i = 0; i < 4; i++) {
            int n = base + i;
            if (n < Nn) {
                g_h[n * 64 + lane]      = usum(a0[i]) + b1a;
                g_h[n * 64 + 32 + lane] = usum(a1[i]) + b1b;
            }
        }
        __syncwarp();
    }
}

// ------------------------------------------------------------------ per-layer precompute:
// PA[n] = h[n]·(W0a+W0c),  PB[n] = h[n]·(W0b−W0c) + b0
__global__ void precompute_kernel(const float* __restrict__ E0, const float* __restrict__ eb0, int Nn) {
    extern __shared__ float sm[];
    float* sWA = sm;            // 4096
    float* sWB = sm + 4096;     // 4096
    float* sb0 = sm + 8192;     // 64
    float* stage = sm + 8256;   // 8 warps * 320 floats

    for (int t = threadIdx.x; t < 4096; t += blockDim.x) {
        int c = t & 3, lane_ = (t >> 2) & 31, kp = t >> 7;
        int k = 2 * kp + (c & 1);
        int col = lane_ + ((c & 2) ? 32 : 0);
        float wC = E0[(128 + k) * 64 + col];
        sWA[t] = E0[k * 64 + col] + wC;
        sWB[t] = E0[(64 + k) * 64 + col] - wC;
    }
    if (threadIdx.x < 64) sb0[threadIdx.x] = eb0[threadIdx.x];
    __syncthreads();

    int lane = threadIdx.x & 31;
    int wid  = threadIdx.x >> 5;
    float* wbase = stage + wid * 320;
    float2* nP = reinterpret_cast<float2*>(wbase);
    const ulonglong2* WAv = reinterpret_cast<const ulonglong2*>(sWA);
    const ulonglong2* WBv = reinterpret_cast<const ulonglong2*>(sWB);
    const unsigned long long* nU = reinterpret_cast<const unsigned long long*>(nP);

    int wg = blockIdx.x * (blockDim.x >> 5) + wid;
    int ws = gridDim.x * (blockDim.x >> 5);
    for (int base = wg * 4; base < Nn; base += ws * 4) {
#pragma unroll
        for (int i = 0; i < 4; i++) {
            int n = base + i;
            nP[lane * 5 + i] = (n < Nn) ? reinterpret_cast<const float2*>(g_h + n * 64)[lane]
                                        : make_float2(0.f, 0.f);
        }
        __syncwarp();

        unsigned long long aA0[4] = {0,0,0,0}, aA1[4] = {0,0,0,0};
        unsigned long long aB0[4] = {0,0,0,0}, aB1[4] = {0,0,0,0};
#pragma unroll 4
        for (int kp = 0; kp < 32; kp++) {
            ulonglong2 wa = WAv[kp * 32 + lane];
            ulonglong2 wb = WBv[kp * 32 + lane];
#pragma unroll
            for (int i = 0; i < 4; i++) {
                unsigned long long v = nU[kp * 5 + i];
                ffma2(aA0[i], v, wa.x); ffma2(aA1[i], v, wa.y);
                ffma2(aB0[i], v, wb.x); ffma2(aB1[i], v, wb.y);
            }
        }
        float b0a = sb0[lane], b0b = sb0[lane + 32];
#pragma unroll
        for (int i = 0; i < 4; i++) {
            int n = base + i;
            if (n < Nn) {
                g_PA[n * 64 + lane]      = usum(aA0[i]);
                g_PA[n * 64 + 32 + lane] = usum(aA1[i]);
                g_PB[n * 64 + lane]      = usum(aB0[i]) + b0a;
                g_PB[n * 64 + 32 + lane] = usum(aB1[i]) + b0b;
            }
        }
        __syncwarp();
    }
}

// ------------------------------------------------------------------ edge scatter (v4 reds)
// lane covers 4 channels; half-warps cover 2 edges concurrently; 8 edges per pass.
// hidden = elu(PA[src] + PB[dst] + pos_diff·Wp) → red.v4 into g_agg[dst]
__global__ void edge_scatter_kernel(const float* __restrict__ Wp, int Ecnt) {
    int lane = threadIdx.x & 31;
    int wid  = threadIdx.x >> 5;
    int slot = lane >> 4;          // 0/1: which edge of the pair
    int ch   = (lane & 15) * 4;    // channel base (0..60)

    float4 wp0 = __ldg(reinterpret_cast<const float4*>(Wp + ch));
    float4 wp1 = __ldg(reinterpret_cast<const float4*>(Wp + 64 + ch));
    float4 wp2 = __ldg(reinterpret_cast<const float4*>(Wp + 128 + ch));

    const float4* pd4 = reinterpret_cast<const float4*>(g_pd);

    int wg = blockIdx.x * (blockDim.x >> 5) + wid;
    int ws = gridDim.x * (blockDim.x >> 5);
    for (int base = wg * 8; base < Ecnt; base += ws * 8) {
        int ev[4], dv[4];
        float4 pa[4], pb[4], pd[4];
#pragma unroll
        for (int p = 0; p < 4; p++) {
            int e = base + p * 2 + slot;
            ev[p] = e;
            if (e < Ecnt) {
                int s = __ldg(&g_src[e]);
                int d = __ldg(&g_dst[e]);
                dv[p] = d;
                pa[p] = __ldg(reinterpret_cast<const float4*>(g_PA + (size_t)s * 64 + ch));
                pb[p] = __ldg(reinterpret_cast<const float4*>(g_PB + (size_t)d * 64 + ch));
                pd[p] = __ldg(&pd4[e]);
            } else {
                dv[p] = -1;
            }
        }
#pragma unroll
        for (int p = 0; p < 4; p++) {
            if (dv[p] >= 0) {
                float hx = elu_f(pa[p].x + pb[p].x + pd[p].x * wp0.x + pd[p].y * wp1.x + pd[p].z * wp2.x);
                float hy = elu_f(pa[p].y + pb[p].y + pd[p].x * wp0.y + pd[p].y * wp1.y + pd[p].z * wp2.y);
                float hz = elu_f(pa[p].z + pb[p].z + pd[p].x * wp0.z + pd[p].y * wp1.z + pd[p].z * wp2.z);
                float hw = elu_f(pa[p].w + pb[p].w + pd[p].x * wp0.w + pd[p].y * wp1.w + pd[p].z * wp2.w);
                red_add_v4(&g_agg[(size_t)dv[p] * 64 + ch], hx, hy, hz, hw);
            }
        }
    }
}

// ------------------------------------------------------------------ fused node update:
// agg = Hsum[n]·eW1 + deg[n]·eb1 ; u = elu([h, agg]·nW0 + nb0)·nW1 + nb1 ; h += u
__global__ void node_fused_kernel(const float* __restrict__ E1, const float* __restrict__ eb1,
                                  const float* __restrict__ W0, const float* __restrict__ b0,
                                  const float* __restrict__ W1, const float* __restrict__ b1,
                                  int Nn) {
    extern __shared__ float sm[];
    float* sE1 = sm;                 // 4096
    float* sW0 = sm + 4096;          // 8192
    float* sW1 = sm + 12288;         // 4096
    float* seb1 = sm + 16384;        // 64
    float* snb0 = sm + 16448;        // 64
    float* snb1 = sm + 16512;        // 64
    float* stage = sm + 16576;       // 8 warps * 640

    for (int t = threadIdx.x; t < 4096; t += blockDim.x) {
        int c = t & 3, lane_ = (t >> 2) & 31, kp = t >> 7;
        int k = 2 * kp + (c & 1);
        int col = lane_ + ((c & 2) ? 32 : 0);
        sE1[t] = E1[k * 64 + col];
        sW1[t] = W1[k * 64 + col];
    }
    for (int t = threadIdx.x; t < 8192; t += blockDim.x) {
        int c = t & 3, lane_ = (t >> 2) & 31, kp = t >> 7;
        int k = 2 * kp + (c & 1);
        int col = lane_ + ((c & 2) ? 32 : 0);
        sW0[t] = W0[k * 64 + col];
    }
    if (threadIdx.x < 64) {
        seb1[threadIdx.x] = eb1[threadIdx.x];
        snb0[threadIdx.x] = b0[threadIdx.x];
        snb1[threadIdx.x] = b1[threadIdx.x];
    }
    __syncthreads();

    int lane = threadIdx.x & 31;
    int wid  = threadIdx.x >> 5;
    float* wbase = stage + wid * 640;
    float2* nP = reinterpret_cast<float2*>(wbase);
    const ulonglong2* E1v = reinterpret_cast<const ulonglong2*>(sE1);
    const ulonglong2* W0v = reinterpret_cast<const ulonglong2*>(sW0);
    const ulonglong2* W1v = reinterpret_cast<const ulonglong2*>(sW1);
    const unsigned long long* nU = reinterpret_cast<const unsigned long long*>(nP);
    float* hF = wbase;

    int wg = blockIdx.x * (blockDim.x >> 5) + wid;
    int ws = gridDim.x * (blockDim.x >> 5);
    for (int base = wg * 4; base < Nn; base += ws * 4) {
        float degf[4];
#pragma unroll
        for (int i = 0; i < 4; i++) {
            int n = base + i;
            if (n < Nn) {
                nP[lane * 5 + i]        = reinterpret_cast<const float2*>(g_h + n * 64)[lane];
                nP[(32 + lane) * 5 + i] = reinterpret_cast<const float2*>(g_agg + n * 64)[lane];
                degf[i] = (float)__ldg(&g_deg[n]);
            } else {
                nP[lane * 5 + i]        = make_float2(0.f, 0.f);
                nP[(32 + lane) * 5 + i] = make_float2(0.f, 0.f);
                degf[i] = 0.f;
            }
        }
        __syncwarp();

        // ---- GEMM1: agg = Hsum·E1 + deg·eb1
        unsigned long long a0[4] = {0,0,0,0}, a1[4] = {0,0,0,0};
#pragma unroll 4
        for (int kp = 0; kp < 32; kp++) {
            ulonglong2 w = E1v[kp * 32 + lane];
#pragma unroll
            for (int i = 0; i < 4; i++) {
                unsigned long long v = nU[(32 + kp) * 5 + i];
                ffma2(a0[i], v, w.x); ffma2(a1[i], v, w.y);
            }
        }
        float e1a = seb1[lane], e1b = seb1[lane + 32];
        float aggL[4], aggH[4];
#pragma unroll
        for (int i = 0; i < 4; i++) {
            aggL[i] = usum(a0[i]) + degf[i] * e1a;
            aggH[i] = usum(a1[i]) + degf[i] * e1b;
        }
        __syncwarp();
        {
            int rL = ((32 + (lane >> 1)) * 5) * 2 + (lane & 1);
            int rH = ((48 + (lane >> 1)) * 5) * 2 + (lane & 1);
#pragma unroll
            for (int i = 0; i < 4; i++) {
                hF[rL + 2 * i] = aggL[i];
                hF[rH + 2 * i] = aggH[i];
            }
        }
        __syncwarp();

        // ---- GEMM2: hidden = elu([h, agg]·W0 + b0)
        unsigned long long c0[4] = {0,0,0,0}, c1[4] = {0,0,0,0};
#pragma unroll 4
        for (int kp = 0; kp < 64; kp++) {
            ulonglong2 w = W0v[kp * 32 + lane];
#pragma unroll
            for (int i = 0; i < 4; i++) {
                unsigned long long v = nU[kp * 5 + i];
                ffma2(c0[i], v, w.x); ffma2(c1[i], v, w.y);
            }
        }
        float b0a = snb0[lane], b0b = snb0[lane + 32];
        float hL[4], hH[4];
#pragma unroll
        for (int i = 0; i < 4; i++) {
            hL[i] = elu_f(usum(c0[i]) + b0a);
            hH[i] = elu_f(usum(c1[i]) + b0b);
        }
        __syncwarp();
        {
            int rL = ((lane >> 1) * 5) * 2 + (lane & 1);
            int rH = ((16 + (lane >> 1)) * 5) * 2 + (lane & 1);
#pragma unroll
            for (int i = 0; i < 4; i++) {
                hF[rL + 2 * i] = hL[i];
                hF[rH + 2 * i] = hH[i];
            }
        }
        __syncwarp();

        // ---- GEMM3: u = hidden·W1 + b1 ; h += u
        unsigned long long d0[4] = {0,0,0,0}, d1[4] = {0,0,0,0};
#pragma unroll 4
        for (int kp = 0; kp < 32; kp++) {
            ulonglong2 w = W1v[kp * 32 + lane];
#pragma unroll
            for (int i = 0; i < 4; i++) {
                unsigned long long v = nU[kp * 5 + i];
                ffma2(d0[i], v, w.x); ffma2(d1[i], v, w.y);
            }
        }
        float b1a = snb1[lane], b1b = snb1[lane + 32];
#pragma unroll
        for (int i = 0; i < 4; i++) {
            int n = base + i;
            if (n < Nn) {
                float old0 = g_h[n * 64 + lane];
                float old1 = g_h[n * 64 + 32 + lane];
                g_h[n * 64 + lane]      = old0 + usum(d0[i]) + b1a;
                g_h[n * 64 + 32 + lane] = old1 + usum(d1[i]) + b1b;
            }
        }
        __syncwarp();
    }
}

// ------------------------------------------------------------------ decoder (f32x2)
__global__ void decoder_kernel(const float* __restrict__ W0, const float* __restrict__ b0,
                               const float* __restrict__ W1, const float* __restrict__ b1,
                               float* __restrict__ out, int Nn) {
    extern __shared__ float sm[];
    float* sW0 = sm;            // 4096, kpair-packed
    float* sW1 = sm + 4096;     // 192 (row-major [64][3])
    float* sb0 = sm + 4288;     // 64
    float* sb1v = sm + 4352;    // 3 (+pad)
    float* stage = sm + 4356;   // 8 warps * 320

    for (int t = threadIdx.x; t < 4096; t += blockDim.x) {
        int c = t & 3, lane_ = (t >> 2) & 31, kp = t >> 7;
        int k = 2 * kp + (c & 1);
        int col = lane_ + ((c & 2) ? 32 : 0);
        sW0[t] = W0[k * 64 + col];
    }
    for (int t = threadIdx.x; t < 192; t += blockDim.x) sW1[t] = W1[t];
    if (threadIdx.x < 64) sb0[threadIdx.x] = b0[threadIdx.x];
    if (threadIdx.x < 3)  sb1v[threadIdx.x] = b1[threadIdx.x];
    __syncthreads();

    int lane = threadIdx.x & 31;
    int wid  = threadIdx.x >> 5;
    float* wbase = stage + wid * 320;
    float2* nP = reinterpret_cast<float2*>(wbase);
    const ulonglong2* W0v = reinterpret_cast<const ulonglong2*>(sW0);
    const unsigned long long* nU = reinterpret_cast<const unsigned long long*>(nP);
    const float2* H2 = reinterpret_cast<const float2*>(g_h);

    int wg = blockIdx.x * (blockDim.x >> 5) + wid;
    int ws = gridDim.x * (blockDim.x >> 5);
    for (int base = wg * 4; base < Nn; base += ws * 4) {
#pragma unroll
        for (int i = 0; i < 4; i++) {
            int n = base + i;
            nP[lane * 5 + i] = (n < Nn) ? __ldg(&H2[(size_t)n * 32 + lane]) : make_float2(0.f, 0.f);
        }
        __syncwarp();

        unsigned long long a0[4] = {0,0,0,0}, a1[4] = {0,0,0,0};
#pragma unroll 4
        for (int kp = 0; kp < 32; kp++) {
            ulonglong2 w = W0v[kp * 32 + lane];
#pragma unroll
            for (int i = 0; i < 4; i++) {
                unsigned long long v = nU[kp * 5 + i];
                ffma2(a0[i], v, w.x); ffma2(a1[i], v, w.y);
            }
        }
        float b0a = sb0[lane], b0b = sb0[lane + 32];
        float w1L0 = sW1[lane * 3 + 0], w1L1 = sW1[lane * 3 + 1], w1L2 = sW1[lane * 3 + 2];
        float w1H0 = sW1[(lane + 32) * 3 + 0], w1H1 = sW1[(lane + 32) * 3 + 1], w1H2 = sW1[(lane + 32) * 3 + 2];
#pragma unroll
        for (int i = 0; i < 4; i++) {
            int n = base + i;
            float hid0 = elu_f(usum(a0[i]) + b0a);
            float hid1 = elu_f(usum(a1[i]) + b0b);
            float p0 = hid0 * w1L0 + hid1 * w1H0;
            float p1 = hid0 * w1L1 + hid1 * w1H1;
            float p2 = hid0 * w1L2 + hid1 * w1H2;
#pragma unroll
            for (int off = 16; off; off >>= 1) {
                p0 += __shfl_xor_sync(~0u, p0, off);
                p1 += __shfl_xor_sync(~0u, p1, off);
                p2 += __shfl_xor_sync(~0u, p2, off);
            }
            if (lane == 0 && n < Nn) {
                out[n * 3 + 0] = p0 + sb1v[0];
                out[n * 3 + 1] = p1 + sb1v[1];
                out[n * 3 + 2] = p2 + sb1v[2];
            }
        }
        __syncwarp();
    }
}

// ------------------------------------------------------------------ launch
extern "C" void kernel_launch(void* const* d_in, const int* in_sizes, int n_in,
                              void* d_out, int out_size) {
    const float* x      = (const float*)d_in[0];
    const float* pos    = (const float*)d_in[1];
    const int*   ei     = (const int*)d_in[2];   // dtype auto-detected on device
    const float* enc_W0 = (const float*)d_in[3];
    const float* enc_b0 = (const float*)d_in[4];
    const float* enc_W1 = (const float*)d_in[5];
    const float* enc_b1 = (const float*)d_in[6];
    const float* dec_W0 = (const float*)d_in[7];
    const float* dec_b0 = (const float*)d_in[8];
    const float* dec_W1 = (const float*)d_in[9];
    const float* dec_b1 = (const float*)d_in[10];
    const float* eW0    = (const float*)d_in[11];
    const float* eb0    = (const float*)d_in[12];
    const float* eW1    = (const float*)d_in[13];
    const float* eb1    = (const float*)d_in[14];
    const float* nW0    = (const float*)d_in[15];
    const float* nb0    = (const float*)d_in[16];
    const float* nW1    = (const float*)d_in[17];
    const float* nb1    = (const float*)d_in[18];

    int Nn   = in_sizes[0] / 3;
    int Ecnt = in_sizes[2] / 2;
    if (Ecnt > EMAX) Ecnt = EMAX;
    float* out = (float*)d_out;

    const int ENC_SMEM  = (4416 + 8 * 320) * 4;    // 27,904 B
    const int PRE_SMEM  = (8256 + 8 * 320) * 4;    // 43,264 B
    const int NODE_SMEM = (16576 + 8 * 640) * 4;   // 86,784 B
    const int DEC_SMEM  = (4356 + 8 * 320) * 4;    // 27,664 B
    cudaFuncSetAttribute(precompute_kernel, cudaFuncAttributeMaxDynamicSharedMemorySize, PRE_SMEM);
    cudaFuncSetAttribute(node_fused_kernel, cudaFuncAttributeMaxDynamicSharedMemorySize, NODE_SMEM);

    const int TPB = 256;

    probe_kernel<<<1, 32>>>(ei);
    zero_deg_kernel<<<148, TPB>>>(Nn);
    convert_kernel<<<444, TPB>>>(ei, pos, Ecnt);
    encoder_kernel<<<296, TPB, ENC_SMEM>>>(x, enc_W0, enc_b0, enc_W1, enc_b1, Nn);
    for (int l = 0; l < 2; l++) {
        const float* E0l = eW0 + (size_t)l * 195 * 64;
        precompute_kernel<<<296, TPB, PRE_SMEM>>>(E0l, eb0 + l * 64, Nn);
        zero_agg_kernel<<<444, TPB>>>(Nn * 64 / 4);
        edge_scatter_kernel<<<592, TPB>>>(E0l + 192 * 64, Ecnt);
        node_fused_kernel<<<296, TPB, NODE_SMEM>>>(eW1 + (size_t)l * 64 * 64, eb1 + l * 64,
                                                   nW0 + (size_t)l * 128 * 64, nb0 + l * 64,
                                                   nW1 + (size_t)l * 64 * 64,  nb1 + l * 64,
                                                   Nn);
    }
    decoder_kernel<<<296, TPB, DEC_SMEM>>>(dec_W0, dec_b0, dec_W1, dec_b1, out, Nn);
}

// round 9
// speedup vs baseline: 1.5074x; 1.3081x over previous
#include <cuda_runtime.h>
#include <cuda_bf16.h>

#define NNODE 100000
#define EMAX  1600000
#define CDIM 64

__device__ __align__(16) float g_h[NNODE * CDIM];
__device__ __align__(16) float g_agg[NNODE * CDIM];
__device__ __align__(16) float g_PA[NNODE * CDIM];   // h·WA + pos·Wp
__device__ __align__(16) float g_PB[NNODE * CDIM];   // h·WB + b0 − pos·Wp
__device__ __align__(8)  int2  g_sd[EMAX];
__device__ int   g_deg[NNODE];
__device__ int   g_mode;                              // 1 = int64 indices, 0 = int32

__device__ __forceinline__ float elu_f(float v) {
    return v > 0.f ? v : expm1f(v);
}

// packed fp32x2 helpers (sm_100+)
__device__ __forceinline__ void ffma2(unsigned long long& d, unsigned long long a, unsigned long long b) {
    asm("fma.rn.f32x2 %0, %1, %2, %0;" : "+l"(d) : "l"(a), "l"(b));
}
__device__ __forceinline__ float usum(unsigned long long v) {
    float lo, hi;
    asm("mov.b64 {%0,%1}, %2;" : "=f"(lo), "=f"(hi) : "l"(v));
    return lo + hi;
}
__device__ __forceinline__ void red_add_v4(float* addr, float x, float y, float z, float w) {
    asm volatile("red.global.add.v4.f32 [%0], {%1, %2, %3, %4};"
                 :: "l"(addr), "f"(x), "f"(y), "f"(z), "f"(w) : "memory");
}

// ------------------------------------------------------------------ launch 0: probe dtype + zero deg
__global__ void probe_zero_kernel(const int* __restrict__ w, int Nn) {
    if (blockIdx.x == 0 && threadIdx.x == 0) {
        bool all_odd_zero = true;
        for (int i = 1; i < 64; i += 2)
            if (w[i] != 0) { all_odd_zero = false; break; }
        g_mode = all_odd_zero ? 1 : 0;
    }
    for (int i = blockIdx.x * blockDim.x + threadIdx.x; i < Nn; i += gridDim.x * blockDim.x)
        g_deg[i] = 0;
}

// ------------------------------------------------------------------ launch 1: convert indices + deg + zero agg (layer 0)
__global__ void convert_kernel(const int* __restrict__ w, int Ecnt, int Nn) {
    int mode = g_mode;
    for (int e = blockIdx.x * blockDim.x + threadIdx.x; e < Ecnt; e += gridDim.x * blockDim.x) {
        int s, d;
        if (mode) { s = w[2 * e]; d = w[2 * (Ecnt + e)]; }
        else      { s = w[e];     d = w[Ecnt + e]; }
        s = min(max(s, 0), NNODE - 1);
        d = min(max(d, 0), NNODE - 1);
        g_sd[e] = make_int2(s, d);
        atomicAdd(&g_deg[d], 1);
    }
    float4* p = reinterpret_cast<float4*>(g_agg);
    int n4 = Nn * 16;
    for (int i = blockIdx.x * blockDim.x + threadIdx.x; i < n4; i += gridDim.x * blockDim.x)
        p[i] = make_float4(0.f, 0.f, 0.f, 0.f);
}

// ------------------------------------------------------------------ launch 2: encoder + precompute(layer 0) fused
// h = elu(x·W0e + b0e)·W1e + b1e ; PA = h·WA + pos·Wp ; PB = h·WB + b0 − pos·Wp
__global__ void enc_pre_kernel(const float* __restrict__ x, const float* __restrict__ pos,
                               const float* __restrict__ W0e, const float* __restrict__ b0e,
                               const float* __restrict__ W1e, const float* __restrict__ b1e,
                               const float* __restrict__ E0, const float* __restrict__ eb0,
                               int Nn) {
    extern __shared__ float sm[];
    float* sW1 = sm;             // 4096 kpair-packed (enc W1)
    float* sWA = sm + 4096;      // 4096
    float* sWB = sm + 8192;      // 4096
    float* sW0 = sm + 12288;     // 192 (enc W0)
    float* sWp = sm + 12480;     // 192 plain [3][64]
    float* sbe0 = sm + 12672;    // 64
    float* sbe1 = sm + 12736;    // 64
    float* sb0  = sm + 12800;    // 64 (edge b0)
    float* stage = sm + 12864;   // 8 warps * 320

    for (int t = threadIdx.x; t < 4096; t += blockDim.x) {
        int c = t & 3, lane_ = (t >> 2) & 31, kp = t >> 7;
        int k = 2 * kp + (c & 1);
        int col = lane_ + ((c & 2) ? 32 : 0);
        sW1[t] = W1e[k * 64 + col];
        float wC = E0[(128 + k) * 64 + col];
        sWA[t] = E0[k * 64 + col] + wC;
        sWB[t] = E0[(64 + k) * 64 + col] - wC;
    }
    for (int t = threadIdx.x; t < 192; t += blockDim.x) {
        sW0[t] = W0e[t];
        sWp[t] = E0[(192 + (t >> 6)) * 64 + (t & 63)];
    }
    if (threadIdx.x < 64) {
        sbe0[threadIdx.x] = b0e[threadIdx.x];
        sbe1[threadIdx.x] = b1e[threadIdx.x];
        sb0[threadIdx.x]  = eb0[threadIdx.x];
    }
    __syncthreads();

    int lane = threadIdx.x & 31;
    int wid  = threadIdx.x >> 5;
    float* wbase = stage + wid * 320;
    const ulonglong2* W1v = reinterpret_cast<const ulonglong2*>(sW1);
    const ulonglong2* WAv = reinterpret_cast<const ulonglong2*>(sWA);
    const ulonglong2* WBv = reinterpret_cast<const ulonglong2*>(sWB);
    const unsigned long long* nU = reinterpret_cast<const unsigned long long*>(wbase);
    float* hF = wbase;

    int rL = ((lane >> 1) * 5) * 2 + (lane & 1);
    int rH = ((16 + (lane >> 1)) * 5) * 2 + (lane & 1);

    int wg = blockIdx.x * (blockDim.x >> 5) + wid;
    int ws = gridDim.x * (blockDim.x >> 5);
    for (int base = wg * 4; base < Nn; base += ws * 4) {
        float p0v[4], p1v[4], p2v[4];
#pragma unroll
        for (int i = 0; i < 4; i++) {
            int n = base + i;
            float h0 = 0.f, h1 = 0.f;
            if (n < Nn) {
                float x0 = __ldg(&x[n * 3 + 0]), x1 = __ldg(&x[n * 3 + 1]), x2 = __ldg(&x[n * 3 + 2]);
                h0 = elu_f(x0 * sW0[lane]      + x1 * sW0[64 + lane]      + x2 * sW0[128 + lane]      + sbe0[lane]);
                h1 = elu_f(x0 * sW0[lane + 32] + x1 * sW0[64 + lane + 32] + x2 * sW0[128 + lane + 32] + sbe0[lane + 32]);
                p0v[i] = __ldg(&pos[n * 3 + 0]);
                p1v[i] = __ldg(&pos[n * 3 + 1]);
                p2v[i] = __ldg(&pos[n * 3 + 2]);
            } else { p0v[i] = p1v[i] = p2v[i] = 0.f; }
            hF[rL + 2 * i] = h0;
            hF[rH + 2 * i] = h1;
        }
        __syncwarp();

        // GEMM: h = hid·W1e + b1e
        unsigned long long a0[4] = {0,0,0,0}, a1[4] = {0,0,0,0};
#pragma unroll 4
        for (int kp = 0; kp < 32; kp++) {
            ulonglong2 w = W1v[kp * 32 + lane];
#pragma unroll
            for (int i = 0; i < 4; i++) {
                unsigned long long v = nU[kp * 5 + i];
                ffma2(a0[i], v, w.x); ffma2(a1[i], v, w.y);
            }
        }
        float b1a = sbe1[lane], b1b = sbe1[lane + 32];
        float hL[4], hH[4];
#pragma unroll
        for (int i = 0; i < 4; i++) {
            hL[i] = usum(a0[i]) + b1a;
            hH[i] = usum(a1[i]) + b1b;
            int n = base + i;
            if (n < Nn) {
                g_h[n * 64 + lane]      = hL[i];
                g_h[n * 64 + 32 + lane] = hH[i];
            }
        }
        __syncwarp();
#pragma unroll
        for (int i = 0; i < 4; i++) {
            hF[rL + 2 * i] = hL[i];
            hF[rH + 2 * i] = hH[i];
        }
        __syncwarp();

        // GEMMs: PA = h·WA + pos·Wp ; PB = h·WB + b0 − pos·Wp
        unsigned long long aA0[4] = {0,0,0,0}, aA1[4] = {0,0,0,0};
        unsigned long long aB0[4] = {0,0,0,0}, aB1[4] = {0,0,0,0};
#pragma unroll 4
        for (int kp = 0; kp < 32; kp++) {
            ulonglong2 wa = WAv[kp * 32 + lane];
            ulonglong2 wb = WBv[kp * 32 + lane];
#pragma unroll
            for (int i = 0; i < 4; i++) {
                unsigned long long v = nU[kp * 5 + i];
                ffma2(aA0[i], v, wa.x); ffma2(aA1[i], v, wa.y);
                ffma2(aB0[i], v, wb.x); ffma2(aB1[i], v, wb.y);
            }
        }
        float b0a = sb0[lane], b0b = sb0[lane + 32];
        float wpL0 = sWp[lane], wpL1 = sWp[64 + lane], wpL2 = sWp[128 + lane];
        float wpH0 = sWp[lane + 32], wpH1 = sWp[64 + lane + 32], wpH2 = sWp[128 + lane + 32];
#pragma unroll
        for (int i = 0; i < 4; i++) {
            int n = base + i;
            if (n < Nn) {
                float wpa = p0v[i] * wpL0 + p1v[i] * wpL1 + p2v[i] * wpL2;
                float wpb = p0v[i] * wpH0 + p1v[i] * wpH1 + p2v[i] * wpH2;
                g_PA[n * 64 + lane]      = usum(aA0[i]) + wpa;
                g_PA[n * 64 + 32 + lane] = usum(aA1[i]) + wpb;
                g_PB[n * 64 + lane]      = usum(aB0[i]) + b0a - wpa;
                g_PB[n * 64 + 32 + lane] = usum(aB1[i]) + b0b - wpb;
            }
        }
        __syncwarp();
    }
}

// ------------------------------------------------------------------ launch 3 (PROFILED): edge scatter
// hidden = elu(PA[s] + PB[d]) → red.v4 into g_agg[d].  No pd, no SMEM.
__global__ void edge_scatter_kernel(int Ecnt) {
    int lane = threadIdx.x & 31;
    int wid  = threadIdx.x >> 5;
    int slot = lane >> 4;          // 0/1: which edge of the pair
    int ch   = (lane & 15) * 4;    // channel base (0..60)

    int wg = blockIdx.x * (blockDim.x >> 5) + wid;
    int ws = gridDim.x * (blockDim.x >> 5);
    for (int base = wg * 8; base < Ecnt; base += ws * 8) {
        int2 ed[4];
        float4 pa[4], pb[4];
#pragma unroll
        for (int p = 0; p < 4; p++) {
            int e = base + p * 2 + slot;
            ed[p] = (e < Ecnt) ? __ldg(&g_sd[e]) : make_int2(-1, -1);
        }
#pragma unroll
        for (int p = 0; p < 4; p++) {
            if (ed[p].x >= 0) {
                pa[p] = __ldg(reinterpret_cast<const float4*>(g_PA + (size_t)ed[p].x * 64 + ch));
                pb[p] = __ldg(reinterpret_cast<const float4*>(g_PB + (size_t)ed[p].y * 64 + ch));
            }
        }
#pragma unroll
        for (int p = 0; p < 4; p++) {
            if (ed[p].x >= 0) {
                float hx = elu_f(pa[p].x + pb[p].x);
                float hy = elu_f(pa[p].y + pb[p].y);
                float hz = elu_f(pa[p].z + pb[p].z);
                float hw = elu_f(pa[p].w + pb[p].w);
                red_add_v4(&g_agg[(size_t)ed[p].y * 64 + ch], hx, hy, hz, hw);
            }
        }
    }
}

// ------------------------------------------------------------------ precompute (layer 1) + zero agg
__global__ void pre_zero_kernel(const float* __restrict__ E0, const float* __restrict__ eb0,
                                const float* __restrict__ pos, int Nn) {
    extern __shared__ float sm[];
    float* sWA = sm;            // 4096
    float* sWB = sm + 4096;     // 4096
    float* sWp = sm + 8192;     // 192
    float* sb0 = sm + 8384;     // 64
    float* stage = sm + 8448;   // 8 warps * 320

    for (int t = threadIdx.x; t < 4096; t += blockDim.x) {
        int c = t & 3, lane_ = (t >> 2) & 31, kp = t >> 7;
        int k = 2 * kp + (c & 1);
        int col = lane_ + ((c & 2) ? 32 : 0);
        float wC = E0[(128 + k) * 64 + col];
        sWA[t] = E0[k * 64 + col] + wC;
        sWB[t] = E0[(64 + k) * 64 + col] - wC;
    }
    for (int t = threadIdx.x; t < 192; t += blockDim.x)
        sWp[t] = E0[(192 + (t >> 6)) * 64 + (t & 63)];
    if (threadIdx.x < 64) sb0[threadIdx.x] = eb0[threadIdx.x];
    __syncthreads();

    int lane = threadIdx.x & 31;
    int wid  = threadIdx.x >> 5;
    float* wbase = stage + wid * 320;
    float2* nP = reinterpret_cast<float2*>(wbase);
    const ulonglong2* WAv = reinterpret_cast<const ulonglong2*>(sWA);
    const ulonglong2* WBv = reinterpret_cast<const ulonglong2*>(sWB);
    const unsigned long long* nU = reinterpret_cast<const unsigned long long*>(nP);

    int wg = blockIdx.x * (blockDim.x >> 5) + wid;
    int ws = gridDim.x * (blockDim.x >> 5);
    for (int base = wg * 4; base < Nn; base += ws * 4) {
        float p0v[4], p1v[4], p2v[4];
#pragma unroll
        for (int i = 0; i < 4; i++) {
            int n = base + i;
            if (n < Nn) {
                nP[lane * 5 + i] = reinterpret_cast<const float2*>(g_h + n * 64)[lane];
                p0v[i] = __ldg(&pos[n * 3 + 0]);
                p1v[i] = __ldg(&pos[n * 3 + 1]);
                p2v[i] = __ldg(&pos[n * 3 + 2]);
                reinterpret_cast<float2*>(g_agg + n * 64)[lane] = make_float2(0.f, 0.f);
            } else {
                nP[lane * 5 + i] = make_float2(0.f, 0.f);
                p0v[i] = p1v[i] = p2v[i] = 0.f;
            }
        }
        __syncwarp();

        unsigned long long aA0[4] = {0,0,0,0}, aA1[4] = {0,0,0,0};
        unsigned long long aB0[4] = {0,0,0,0}, aB1[4] = {0,0,0,0};
#pragma unroll 4
        for (int kp = 0; kp < 32; kp++) {
            ulonglong2 wa = WAv[kp * 32 + lane];
            ulonglong2 wb = WBv[kp * 32 + lane];
#pragma unroll
            for (int i = 0; i < 4; i++) {
                unsigned long long v = nU[kp * 5 + i];
                ffma2(aA0[i], v, wa.x); ffma2(aA1[i], v, wa.y);
                ffma2(aB0[i], v, wb.x); ffma2(aB1[i], v, wb.y);
            }
        }
        float b0a = sb0[lane], b0b = sb0[lane + 32];
        float wpL0 = sWp[lane], wpL1 = sWp[64 + lane], wpL2 = sWp[128 + lane];
        float wpH0 = sWp[lane + 32], wpH1 = sWp[64 + lane + 32], wpH2 = sWp[128 + lane + 32];
#pragma unroll
        for (int i = 0; i < 4; i++) {
            int n = base + i;
            if (n < Nn) {
                float wpa = p0v[i] * wpL0 + p1v[i] * wpL1 + p2v[i] * wpL2;
                float wpb = p0v[i] * wpH0 + p1v[i] * wpH1 + p2v[i] * wpH2;
                g_PA[n * 64 + lane]      = usum(aA0[i]) + wpa;
                g_PA[n * 64 + 32 + lane] = usum(aA1[i]) + wpb;
                g_PB[n * 64 + lane]      = usum(aB0[i]) + b0a - wpa;
                g_PB[n * 64 + 32 + lane] = usum(aB1[i]) + b0b - wpb;
            }
        }
        __syncwarp();
    }
}

// ------------------------------------------------------------------ fused node update
__global__ void node_fused_kernel(const float* __restrict__ E1, const float* __restrict__ eb1,
                                  const float* __restrict__ W0, const float* __restrict__ b0,
                                  const float* __restrict__ W1, const float* __restrict__ b1,
                                  int Nn) {
    extern __shared__ float sm[];
    float* sE1 = sm;                 // 4096
    float* sW0 = sm + 4096;          // 8192
    float* sW1 = sm + 12288;         // 4096
    float* seb1 = sm + 16384;        // 64
    float* snb0 = sm + 16448;        // 64
    float* snb1 = sm + 16512;        // 64
    float* stage = sm + 16576;       // 8 warps * 640

    for (int t = threadIdx.x; t < 4096; t += blockDim.x) {
        int c = t & 3, lane_ = (t >> 2) & 31, kp = t >> 7;
        int k = 2 * kp + (c & 1);
        int col = lane_ + ((c & 2) ? 32 : 0);
        sE1[t] = E1[k * 64 + col];
        sW1[t] = W1[k * 64 + col];
    }
    for (int t = threadIdx.x; t < 8192; t += blockDim.x) {
        int c = t & 3, lane_ = (t >> 2) & 31, kp = t >> 7;
        int k = 2 * kp + (c & 1);
        int col = lane_ + ((c & 2) ? 32 : 0);
        sW0[t] = W0[k * 64 + col];
    }
    if (threadIdx.x < 64) {
        seb1[threadIdx.x] = eb1[threadIdx.x];
        snb0[threadIdx.x] = b0[threadIdx.x];
        snb1[threadIdx.x] = b1[threadIdx.x];
    }
    __syncthreads();

    int lane = threadIdx.x & 31;
    int wid  = threadIdx.x >> 5;
    float* wbase = stage + wid * 640;
    float2* nP = reinterpret_cast<float2*>(wbase);
    const ulonglong2* E1v = reinterpret_cast<const ulonglong2*>(sE1);
    const ulonglong2* W0v = reinterpret_cast<const ulonglong2*>(sW0);
    const ulonglong2* W1v = reinterpret_cast<const ulonglong2*>(sW1);
    const unsigned long long* nU = reinterpret_cast<const unsigned long long*>(nP);
    float* hF = wbase;

    int wg = blockIdx.x * (blockDim.x >> 5) + wid;
    int ws = gridDim.x * (blockDim.x >> 5);
    for (int base = wg * 4; base < Nn; base += ws * 4) {
        float degf[4];
#pragma unroll
        for (int i = 0; i < 4; i++) {
            int n = base + i;
            if (n < Nn) {
                nP[lane * 5 + i]        = reinterpret_cast<const float2*>(g_h + n * 64)[lane];
                nP[(32 + lane) * 5 + i] = reinterpret_cast<const float2*>(g_agg + n * 64)[lane];
                degf[i] = (float)__ldg(&g_deg[n]);
            } else {
                nP[lane * 5 + i]        = make_float2(0.f, 0.f);
                nP[(32 + lane) * 5 + i] = make_float2(0.f, 0.f);
                degf[i] = 0.f;
            }
        }
        __syncwarp();

        // GEMM1: agg = Hsum·E1 + deg·eb1
        unsigned long long a0[4] = {0,0,0,0}, a1[4] = {0,0,0,0};
#pragma unroll 4
        for (int kp = 0; kp < 32; kp++) {
            ulonglong2 w = E1v[kp * 32 + lane];
#pragma unroll
            for (int i = 0; i < 4; i++) {
                unsigned long long v = nU[(32 + kp) * 5 + i];
                ffma2(a0[i], v, w.x); ffma2(a1[i], v, w.y);
            }
        }
        float e1a = seb1[lane], e1b = seb1[lane + 32];
        float aggL[4], aggH[4];
#pragma unroll
        for (int i = 0; i < 4; i++) {
            aggL[i] = usum(a0[i]) + degf[i] * e1a;
            aggH[i] = usum(a1[i]) + degf[i] * e1b;
        }
        __syncwarp();
        {
            int rL = ((32 + (lane >> 1)) * 5) * 2 + (lane & 1);
            int rH = ((48 + (lane >> 1)) * 5) * 2 + (lane & 1);
#pragma unroll
            for (int i = 0; i < 4; i++) {
                hF[rL + 2 * i] = aggL[i];
                hF[rH + 2 * i] = aggH[i];
            }
        }
        __syncwarp();

        // GEMM2: hidden = elu([h, agg]·W0 + b0)
        unsigned long long c0[4] = {0,0,0,0}, c1[4] = {0,0,0,0};
#pragma unroll 4
        for (int kp = 0; kp < 64; kp++) {
            ulonglong2 w = W0v[kp * 32 + lane];
#pragma unroll
            for (int i = 0; i < 4; i++) {
                unsigned long long v = nU[kp * 5 + i];
                ffma2(c0[i], v, w.x); ffma2(c1[i], v, w.y);
            }
        }
        float b0a = snb0[lane], b0b = snb0[lane + 32];
        float hL[4], hH[4];
#pragma unroll
        for (int i = 0; i < 4; i++) {
            hL[i] = elu_f(usum(c0[i]) + b0a);
            hH[i] = elu_f(usum(c1[i]) + b0b);
        }
        __syncwarp();
        {
            int rL = ((lane >> 1) * 5) * 2 + (lane & 1);
            int rH = ((16 + (lane >> 1)) * 5) * 2 + (lane & 1);
#pragma unroll
            for (int i = 0; i < 4; i++) {
                hF[rL + 2 * i] = hL[i];
                hF[rH + 2 * i] = hH[i];
            }
        }
        __syncwarp();

        // GEMM3: u = hidden·W1 + b1 ; h += u
        unsigned long long d0[4] = {0,0,0,0}, d1[4] = {0,0,0,0};
#pragma unroll 4
        for (int kp = 0; kp < 32; kp++) {
            ulonglong2 w = W1v[kp * 32 + lane];
#pragma unroll
            for (int i = 0; i < 4; i++) {
                unsigned long long v = nU[kp * 5 + i];
                ffma2(d0[i], v, w.x); ffma2(d1[i], v, w.y);
            }
        }
        float b1a = snb1[lane], b1b = snb1[lane + 32];
#pragma unroll
        for (int i = 0; i < 4; i++) {
            int n = base + i;
            if (n < Nn) {
                float old0 = g_h[n * 64 + lane];
                float old1 = g_h[n * 64 + 32 + lane];
                g_h[n * 64 + lane]      = old0 + usum(d0[i]) + b1a;
                g_h[n * 64 + 32 + lane] = old1 + usum(d1[i]) + b1b;
            }
        }
        __syncwarp();
    }
}

// ------------------------------------------------------------------ decoder (f32x2)
__global__ void decoder_kernel(const float* __restrict__ W0, const float* __restrict__ b0,
                               const float* __restrict__ W1, const float* __restrict__ b1,
                               float* __restrict__ out, int Nn) {
    extern __shared__ float sm[];
    float* sW0 = sm;            // 4096, kpair-packed
    float* sW1 = sm + 4096;     // 192 (row-major [64][3])
    float* sb0 = sm + 4288;     // 64
    float* sb1v = sm + 4352;    // 3 (+pad)
    float* stage = sm + 4356;   // 8 warps * 320

    for (int t = threadIdx.x; t < 4096; t += blockDim.x) {
        int c = t & 3, lane_ = (t >> 2) & 31, kp = t >> 7;
        int k = 2 * kp + (c & 1);
        int col = lane_ + ((c & 2) ? 32 : 0);
        sW0[t] = W0[k * 64 + col];
    }
    for (int t = threadIdx.x; t < 192; t += blockDim.x) sW1[t] = W1[t];
    if (threadIdx.x < 64) sb0[threadIdx.x] = b0[threadIdx.x];
    if (threadIdx.x < 3)  sb1v[threadIdx.x] = b1[threadIdx.x];
    __syncthreads();

    int lane = threadIdx.x & 31;
    int wid  = threadIdx.x >> 5;
    float* wbase = stage + wid * 320;
    float2* nP = reinterpret_cast<float2*>(wbase);
    const ulonglong2* W0v = reinterpret_cast<const ulonglong2*>(sW0);
    const unsigned long long* nU = reinterpret_cast<const unsigned long long*>(nP);
    const float2* H2 = reinterpret_cast<const float2*>(g_h);

    int wg = blockIdx.x * (blockDim.x >> 5) + wid;
    int ws = gridDim.x * (blockDim.x >> 5);
    for (int base = wg * 4; base < Nn; base += ws * 4) {
#pragma unroll
        for (int i = 0; i < 4; i++) {
            int n = base + i;
            nP[lane * 5 + i] = (n < Nn) ? __ldg(&H2[(size_t)n * 32 + lane]) : make_float2(0.f, 0.f);
        }
        __syncwarp();

        unsigned long long a0[4] = {0,0,0,0}, a1[4] = {0,0,0,0};
#pragma unroll 4
        for (int kp = 0; kp < 32; kp++) {
            ulonglong2 w = W0v[kp * 32 + lane];
#pragma unroll
            for (int i = 0; i < 4; i++) {
                unsigned long long v = nU[kp * 5 + i];
                ffma2(a0[i], v, w.x); ffma2(a1[i], v, w.y);
            }
        }
        float b0a = sb0[lane], b0b = sb0[lane + 32];
        float w1L0 = sW1[lane * 3 + 0], w1L1 = sW1[lane * 3 + 1], w1L2 = sW1[lane * 3 + 2];
        float w1H0 = sW1[(lane + 32) * 3 + 0], w1H1 = sW1[(lane + 32) * 3 + 1], w1H2 = sW1[(lane + 32) * 3 + 2];
#pragma unroll
        for (int i = 0; i < 4; i++) {
            int n = base + i;
            float hid0 = elu_f(usum(a0[i]) + b0a);
            float hid1 = elu_f(usum(a1[i]) + b0b);
            float p0 = hid0 * w1L0 + hid1 * w1H0;
            float p1 = hid0 * w1L1 + hid1 * w1H1;
            float p2 = hid0 * w1L2 + hid1 * w1H2;
#pragma unroll
            for (int off = 16; off; off >>= 1) {
                p0 += __shfl_xor_sync(~0u, p0, off);
                p1 += __shfl_xor_sync(~0u, p1, off);
                p2 += __shfl_xor_sync(~0u, p2, off);
            }
            if (lane == 0 && n < Nn) {
                out[n * 3 + 0] = p0 + sb1v[0];
                out[n * 3 + 1] = p1 + sb1v[1];
                out[n * 3 + 2] = p2 + sb1v[2];
            }
        }
        __syncwarp();
    }
}

// ------------------------------------------------------------------ launch
extern "C" void kernel_launch(void* const* d_in, const int* in_sizes, int n_in,
                              void* d_out, int out_size) {
    const float* x      = (const float*)d_in[0];
    const float* pos    = (const float*)d_in[1];
    const int*   ei     = (const int*)d_in[2];   // dtype auto-detected on device
    const float* enc_W0 = (const float*)d_in[3];
    const float* enc_b0 = (const float*)d_in[4];
    const float* enc_W1 = (const float*)d_in[5];
    const float* enc_b1 = (const float*)d_in[6];
    const float* dec_W0 = (const float*)d_in[7];
    const float* dec_b0 = (const float*)d_in[8];
    const float* dec_W1 = (const float*)d_in[9];
    const float* dec_b1 = (const float*)d_in[10];
    const float* eW0    = (const float*)d_in[11];
    const float* eb0    = (const float*)d_in[12];
    const float* eW1    = (const float*)d_in[13];
    const float* eb1    = (const float*)d_in[14];
    const float* nW0    = (const float*)d_in[15];
    const float* nb0    = (const float*)d_in[16];
    const float* nW1    = (const float*)d_in[17];
    const float* nb1    = (const float*)d_in[18];

    int Nn   = in_sizes[0] / 3;
    int Ecnt = in_sizes[2] / 2;
    if (Ecnt > EMAX) Ecnt = EMAX;
    float* out = (float*)d_out;

    const int ENCP_SMEM = (12864 + 8 * 320) * 4;   // 61,696 B
    const int PRE_SMEM  = (8448 + 8 * 320) * 4;    // 44,032 B
    const int NODE_SMEM = (16576 + 8 * 640) * 4;   // 86,784 B
    const int DEC_SMEM  = (4356 + 8 * 320) * 4;    // 27,664 B
    cudaFuncSetAttribute(enc_pre_kernel,    cudaFuncAttributeMaxDynamicSharedMemorySize, ENCP_SMEM);
    cudaFuncSetAttribute(pre_zero_kernel,   cudaFuncAttributeMaxDynamicSharedMemorySize, PRE_SMEM);
    cudaFuncSetAttribute(node_fused_kernel, cudaFuncAttributeMaxDynamicSharedMemorySize, NODE_SMEM);

    const int TPB = 256;
    const float* E0_0 = eW0;
    const float* E0_1 = eW0 + (size_t)195 * 64;

    probe_zero_kernel<<<148, TPB>>>(ei, Nn);                                        // 0
    convert_kernel<<<444, TPB>>>(ei, Ecnt, Nn);                                     // 1 (+zero agg l0)
    enc_pre_kernel<<<296, TPB, ENCP_SMEM>>>(x, pos, enc_W0, enc_b0, enc_W1, enc_b1,
                                            E0_0, eb0, Nn);                         // 2
    edge_scatter_kernel<<<592, TPB>>>(Ecnt);                                        // 3  ← profiled
    node_fused_kernel<<<296, TPB, NODE_SMEM>>>(eW1, eb1,
                                               nW0, nb0, nW1, nb1, Nn);             // 4
    pre_zero_kernel<<<296, TPB, PRE_SMEM>>>(E0_1, eb0 + 64, pos, Nn);               // 5
    edge_scatter_kernel<<<592, TPB>>>(Ecnt);                                        // 6
    node_fused_kernel<<<296, TPB, NODE_SMEM>>>(eW1 + (size_t)64 * 64, eb1 + 64,
                                               nW0 + (size_t)128 * 64, nb0 + 64,
                                               nW1 + (size_t)64 * 64,  nb1 + 64, Nn); // 7
    decoder_kernel<<<296, TPB, DEC_SMEM>>>(dec_W0, dec_b0, dec_W1, dec_b1, out, Nn);  // 8
}

// round 10
// speedup vs baseline: 1.8853x; 1.2507x over previous
#include <cuda_runtime.h>
#include <cuda_bf16.h>

#define NNODE 100000
#define EMAX  1600000
#define CDIM 64

__device__ __align__(16) float g_h[NNODE * CDIM];
__device__ __align__(16) float g_agg[NNODE * CDIM];
__device__ __align__(16) float g_PA[NNODE * CDIM];   // h·WA + pos·Wp
__device__ __align__(16) float g_PB[NNODE * CDIM];   // h·WB + b0 − pos·Wp
__device__ __align__(8)  int2  g_sd[EMAX];           // BYTE offsets: (s*256, d*256)
__device__ int   g_deg[NNODE];
__device__ int   g_mode;                              // 1 = int64 indices, 0 = int32

__device__ __forceinline__ float elu_f(float v) {
    return v > 0.f ? v : expm1f(v);
}
// fast elu for the edge hot path: MUFU.EX2-based, abs err ≲ 6e-8
__device__ __forceinline__ float elu_fast(float v) {
    float e = __expf(v) - 1.f;
    return v > 0.f ? v : e;
}

// packed fp32x2 helpers (sm_100+)
__device__ __forceinline__ void ffma2(unsigned long long& d, unsigned long long a, unsigned long long b) {
    asm("fma.rn.f32x2 %0, %1, %2, %0;" : "+l"(d) : "l"(a), "l"(b));
}
__device__ __forceinline__ float usum(unsigned long long v) {
    float lo, hi;
    asm("mov.b64 {%0,%1}, %2;" : "=f"(lo), "=f"(hi) : "l"(v));
    return lo + hi;
}
__device__ __forceinline__ void red_add_v4(float* addr, float x, float y, float z, float w) {
    asm volatile("red.global.add.v4.f32 [%0], {%1, %2, %3, %4};"
                 :: "l"(addr), "f"(x), "f"(y), "f"(z), "f"(w) : "memory");
}

// ------------------------------------------------------------------ launch 0: probe dtype + zero deg
__global__ void probe_zero_kernel(const int* __restrict__ w, int Nn) {
    if (blockIdx.x == 0 && threadIdx.x == 0) {
        bool all_odd_zero = true;
        for (int i = 1; i < 64; i += 2)
            if (w[i] != 0) { all_odd_zero = false; break; }
        g_mode = all_odd_zero ? 1 : 0;
    }
    for (int i = blockIdx.x * blockDim.x + threadIdx.x; i < Nn; i += gridDim.x * blockDim.x)
        g_deg[i] = 0;
}

// ------------------------------------------------------------------ launch 1: convert indices + deg + zero agg (layer 0)
__global__ void convert_kernel(const int* __restrict__ w, int Ecnt, int Nn) {
    int mode = g_mode;
    for (int e = blockIdx.x * blockDim.x + threadIdx.x; e < Ecnt; e += gridDim.x * blockDim.x) {
        int s, d;
        if (mode) { s = w[2 * e]; d = w[2 * (Ecnt + e)]; }
        else      { s = w[e];     d = w[Ecnt + e]; }
        s = min(max(s, 0), NNODE - 1);
        d = min(max(d, 0), NNODE - 1);
        atomicAdd(&g_deg[d], 1);
        g_sd[e] = make_int2(s * 256, d * 256);   // byte offsets into [N,64] fp32 arrays
    }
    float4* p = reinterpret_cast<float4*>(g_agg);
    int n4 = Nn * 16;
    for (int i = blockIdx.x * blockDim.x + threadIdx.x; i < n4; i += gridDim.x * blockDim.x)
        p[i] = make_float4(0.f, 0.f, 0.f, 0.f);
}

// ------------------------------------------------------------------ launch 2: encoder + precompute(layer 0) fused
__global__ void enc_pre_kernel(const float* __restrict__ x, const float* __restrict__ pos,
                               const float* __restrict__ W0e, const float* __restrict__ b0e,
                               const float* __restrict__ W1e, const float* __restrict__ b1e,
                               const float* __restrict__ E0, const float* __restrict__ eb0,
                               int Nn) {
    extern __shared__ float sm[];
    float* sW1 = sm;             // 4096 kpair-packed (enc W1)
    float* sWA = sm + 4096;      // 4096
    float* sWB = sm + 8192;      // 4096
    float* sW0 = sm + 12288;     // 192 (enc W0)
    float* sWp = sm + 12480;     // 192 plain [3][64]
    float* sbe0 = sm + 12672;    // 64
    float* sbe1 = sm + 12736;    // 64
    float* sb0  = sm + 12800;    // 64 (edge b0)
    float* stage = sm + 12864;   // 8 warps * 320

    for (int t = threadIdx.x; t < 4096; t += blockDim.x) {
        int c = t & 3, lane_ = (t >> 2) & 31, kp = t >> 7;
        int k = 2 * kp + (c & 1);
        int col = lane_ + ((c & 2) ? 32 : 0);
        sW1[t] = W1e[k * 64 + col];
        float wC = E0[(128 + k) * 64 + col];
        sWA[t] = E0[k * 64 + col] + wC;
        sWB[t] = E0[(64 + k) * 64 + col] - wC;
    }
    for (int t = threadIdx.x; t < 192; t += blockDim.x) {
        sW0[t] = W0e[t];
        sWp[t] = E0[(192 + (t >> 6)) * 64 + (t & 63)];
    }
    if (threadIdx.x < 64) {
        sbe0[threadIdx.x] = b0e[threadIdx.x];
        sbe1[threadIdx.x] = b1e[threadIdx.x];
        sb0[threadIdx.x]  = eb0[threadIdx.x];
    }
    __syncthreads();

    int lane = threadIdx.x & 31;
    int wid  = threadIdx.x >> 5;
    float* wbase = stage + wid * 320;
    const ulonglong2* W1v = reinterpret_cast<const ulonglong2*>(sW1);
    const ulonglong2* WAv = reinterpret_cast<const ulonglong2*>(sWA);
    const ulonglong2* WBv = reinterpret_cast<const ulonglong2*>(sWB);
    const unsigned long long* nU = reinterpret_cast<const unsigned long long*>(wbase);
    float* hF = wbase;

    int rL = ((lane >> 1) * 5) * 2 + (lane & 1);
    int rH = ((16 + (lane >> 1)) * 5) * 2 + (lane & 1);

    int wg = blockIdx.x * (blockDim.x >> 5) + wid;
    int ws = gridDim.x * (blockDim.x >> 5);
    for (int base = wg * 4; base < Nn; base += ws * 4) {
        float p0v[4], p1v[4], p2v[4];
#pragma unroll
        for (int i = 0; i < 4; i++) {
            int n = base + i;
            float h0 = 0.f, h1 = 0.f;
            if (n < Nn) {
                float x0 = __ldg(&x[n * 3 + 0]), x1 = __ldg(&x[n * 3 + 1]), x2 = __ldg(&x[n * 3 + 2]);
                h0 = elu_f(x0 * sW0[lane]      + x1 * sW0[64 + lane]      + x2 * sW0[128 + lane]      + sbe0[lane]);
                h1 = elu_f(x0 * sW0[lane + 32] + x1 * sW0[64 + lane + 32] + x2 * sW0[128 + lane + 32] + sbe0[lane + 32]);
                p0v[i] = __ldg(&pos[n * 3 + 0]);
                p1v[i] = __ldg(&pos[n * 3 + 1]);
                p2v[i] = __ldg(&pos[n * 3 + 2]);
            } else { p0v[i] = p1v[i] = p2v[i] = 0.f; }
            hF[rL + 2 * i] = h0;
            hF[rH + 2 * i] = h1;
        }
        __syncwarp();

        // GEMM: h = hid·W1e + b1e
        unsigned long long a0[4] = {0,0,0,0}, a1[4] = {0,0,0,0};
#pragma unroll 4
        for (int kp = 0; kp < 32; kp++) {
            ulonglong2 w = W1v[kp * 32 + lane];
#pragma unroll
            for (int i = 0; i < 4; i++) {
                unsigned long long v = nU[kp * 5 + i];
                ffma2(a0[i], v, w.x); ffma2(a1[i], v, w.y);
            }
        }
        float b1a = sbe1[lane], b1b = sbe1[lane + 32];
        float hL[4], hH[4];
#pragma unroll
        for (int i = 0; i < 4; i++) {
            hL[i] = usum(a0[i]) + b1a;
            hH[i] = usum(a1[i]) + b1b;
            int n = base + i;
            if (n < Nn) {
                g_h[n * 64 + lane]      = hL[i];
                g_h[n * 64 + 32 + lane] = hH[i];
            }
        }
        __syncwarp();
#pragma unroll
        for (int i = 0; i < 4; i++) {
            hF[rL + 2 * i] = hL[i];
            hF[rH + 2 * i] = hH[i];
        }
        __syncwarp();

        // GEMMs: PA = h·WA + pos·Wp ; PB = h·WB + b0 − pos·Wp
        unsigned long long aA0[4] = {0,0,0,0}, aA1[4] = {0,0,0,0};
        unsigned long long aB0[4] = {0,0,0,0}, aB1[4] = {0,0,0,0};
#pragma unroll 4
        for (int kp = 0; kp < 32; kp++) {
            ulonglong2 wa = WAv[kp * 32 + lane];
            ulonglong2 wb = WBv[kp * 32 + lane];
#pragma unroll
            for (int i = 0; i < 4; i++) {
                unsigned long long v = nU[kp * 5 + i];
                ffma2(aA0[i], v, wa.x); ffma2(aA1[i], v, wa.y);
                ffma2(aB0[i], v, wb.x); ffma2(aB1[i], v, wb.y);
            }
        }
        float b0a = sb0[lane], b0b = sb0[lane + 32];
        float wpL0 = sWp[lane], wpL1 = sWp[64 + lane], wpL2 = sWp[128 + lane];
        float wpH0 = sWp[lane + 32], wpH1 = sWp[64 + lane + 32], wpH2 = sWp[128 + lane + 32];
#pragma unroll
        for (int i = 0; i < 4; i++) {
            int n = base + i;
            if (n < Nn) {
                float wpa = p0v[i] * wpL0 + p1v[i] * wpL1 + p2v[i] * wpL2;
                float wpb = p0v[i] * wpH0 + p1v[i] * wpH1 + p2v[i] * wpH2;
                g_PA[n * 64 + lane]      = usum(aA0[i]) + wpa;
                g_PA[n * 64 + 32 + lane] = usum(aA1[i]) + wpb;
                g_PB[n * 64 + lane]      = usum(aB0[i]) + b0a - wpa;
                g_PB[n * 64 + 32 + lane] = usum(aB1[i]) + b0b - wpb;
            }
        }
        __syncwarp();
    }
}

// ------------------------------------------------------------------ launch 3 (PROFILED): edge scatter
// hidden = elu(PA[s] + PB[d]) → red.v4 into g_agg[d].  Byte-offset indices, fast elu.
__global__ void edge_scatter_kernel(int Ecnt) {
    int lane = threadIdx.x & 31;
    int wid  = threadIdx.x >> 5;
    int slot = lane >> 4;            // 0/1: which edge of the pair
    int ch16 = (lane & 15) * 16;     // byte offset of 4-channel group

    const char* PAc = reinterpret_cast<const char*>(g_PA) + ch16;
    const char* PBc = reinterpret_cast<const char*>(g_PB) + ch16;
    char*       AGc = reinterpret_cast<char*>(g_agg) + ch16;

    int wg = blockIdx.x * (blockDim.x >> 5) + wid;
    int ws = gridDim.x * (blockDim.x >> 5);
    for (int base = wg * 8; base < Ecnt; base += ws * 8) {
        int2 ed[4];
        float4 pa[4], pb[4];
#pragma unroll
        for (int p = 0; p < 4; p++) {
            int e = base + p * 2 + slot;
            ed[p] = (e < Ecnt) ? __ldg(&g_sd[e]) : make_int2(-1, -1);
        }
#pragma unroll
        for (int p = 0; p < 4; p++) {
            if (ed[p].x >= 0) {
                pa[p] = *reinterpret_cast<const float4*>(PAc + ed[p].x);
                pb[p] = *reinterpret_cast<const float4*>(PBc + ed[p].y);
            }
        }
#pragma unroll
        for (int p = 0; p < 4; p++) {
            if (ed[p].x >= 0) {
                float hx = elu_fast(pa[p].x + pb[p].x);
                float hy = elu_fast(pa[p].y + pb[p].y);
                float hz = elu_fast(pa[p].z + pb[p].z);
                float hw = elu_fast(pa[p].w + pb[p].w);
                red_add_v4(reinterpret_cast<float*>(AGc + ed[p].y), hx, hy, hz, hw);
            }
        }
    }
}

// ------------------------------------------------------------------ precompute (layer 1) + zero agg
__global__ void pre_zero_kernel(const float* __restrict__ E0, const float* __restrict__ eb0,
                                const float* __restrict__ pos, int Nn) {
    extern __shared__ float sm[];
    float* sWA = sm;            // 4096
    float* sWB = sm + 4096;     // 4096
    float* sWp = sm + 8192;     // 192
    float* sb0 = sm + 8384;     // 64
    float* stage = sm + 8448;   // 8 warps * 320

    for (int t = threadIdx.x; t < 4096; t += blockDim.x) {
        int c = t & 3, lane_ = (t >> 2) & 31, kp = t >> 7;
        int k = 2 * kp + (c & 1);
        int col = lane_ + ((c & 2) ? 32 : 0);
        float wC = E0[(128 + k) * 64 + col];
        sWA[t] = E0[k * 64 + col] + wC;
        sWB[t] = E0[(64 + k) * 64 + col] - wC;
    }
    for (int t = threadIdx.x; t < 192; t += blockDim.x)
        sWp[t] = E0[(192 + (t >> 6)) * 64 + (t & 63)];
    if (threadIdx.x < 64) sb0[threadIdx.x] = eb0[threadIdx.x];
    __syncthreads();

    int lane = threadIdx.x & 31;
    int wid  = threadIdx.x >> 5;
    float* wbase = stage + wid * 320;
    float2* nP = reinterpret_cast<float2*>(wbase);
    const ulonglong2* WAv = reinterpret_cast<const ulonglong2*>(sWA);
    const ulonglong2* WBv = reinterpret_cast<const ulonglong2*>(sWB);
    const unsigned long long* nU = reinterpret_cast<const unsigned long long*>(nP);

    int wg = blockIdx.x * (blockDim.x >> 5) + wid;
    int ws = gridDim.x * (blockDim.x >> 5);
    for (int base = wg * 4; base < Nn; base += ws * 4) {
        float p0v[4], p1v[4], p2v[4];
#pragma unroll
        for (int i = 0; i < 4; i++) {
            int n = base + i;
            if (n < Nn) {
                nP[lane * 5 + i] = reinterpret_cast<const float2*>(g_h + n * 64)[lane];
                p0v[i] = __ldg(&pos[n * 3 + 0]);
                p1v[i] = __ldg(&pos[n * 3 + 1]);
                p2v[i] = __ldg(&pos[n * 3 + 2]);
                reinterpret_cast<float2*>(g_agg + n * 64)[lane] = make_float2(0.f, 0.f);
            } else {
                nP[lane * 5 + i] = make_float2(0.f, 0.f);
                p0v[i] = p1v[i] = p2v[i] = 0.f;
            }
        }
        __syncwarp();

        unsigned long long aA0[4] = {0,0,0,0}, aA1[4] = {0,0,0,0};
        unsigned long long aB0[4] = {0,0,0,0}, aB1[4] = {0,0,0,0};
#pragma unroll 4
        for (int kp = 0; kp < 32; kp++) {
            ulonglong2 wa = WAv[kp * 32 + lane];
            ulonglong2 wb = WBv[kp * 32 + lane];
#pragma unroll
            for (int i = 0; i < 4; i++) {
                unsigned long long v = nU[kp * 5 + i];
                ffma2(aA0[i], v, wa.x); ffma2(aA1[i], v, wa.y);
                ffma2(aB0[i], v, wb.x); ffma2(aB1[i], v, wb.y);
            }
        }
        float b0a = sb0[lane], b0b = sb0[lane + 32];
        float wpL0 = sWp[lane], wpL1 = sWp[64 + lane], wpL2 = sWp[128 + lane];
        float wpH0 = sWp[lane + 32], wpH1 = sWp[64 + lane + 32], wpH2 = sWp[128 + lane + 32];
#pragma unroll
        for (int i = 0; i < 4; i++) {
            int n = base + i;
            if (n < Nn) {
                float wpa = p0v[i] * wpL0 + p1v[i] * wpL1 + p2v[i] * wpL2;
                float wpb = p0v[i] * wpH0 + p1v[i] * wpH1 + p2v[i] * wpH2;
                g_PA[n * 64 + lane]      = usum(aA0[i]) + wpa;
                g_PA[n * 64 + 32 + lane] = usum(aA1[i]) + wpb;
                g_PB[n * 64 + lane]      = usum(aB0[i]) + b0a - wpa;
                g_PB[n * 64 + 32 + lane] = usum(aB1[i]) + b0b - wpb;
            }
        }
        __syncwarp();
    }
}

// ------------------------------------------------------------------ fused node update
__global__ void node_fused_kernel(const float* __restrict__ E1, const float* __restrict__ eb1,
                                  const float* __restrict__ W0, const float* __restrict__ b0,
                                  const float* __restrict__ W1, const float* __restrict__ b1,
                                  int Nn) {
    extern __shared__ float sm[];
    float* sE1 = sm;                 // 4096
    float* sW0 = sm + 4096;          // 8192
    float* sW1 = sm + 12288;         // 4096
    float* seb1 = sm + 16384;        // 64
    float* snb0 = sm + 16448;        // 64
    float* snb1 = sm + 16512;        // 64
    float* stage = sm + 16576;       // 8 warps * 640

    for (int t = threadIdx.x; t < 4096; t += blockDim.x) {
        int c = t & 3, lane_ = (t >> 2) & 31, kp = t >> 7;
        int k = 2 * kp + (c & 1);
        int col = lane_ + ((c & 2) ? 32 : 0);
        sE1[t] = E1[k * 64 + col];
        sW1[t] = W1[k * 64 + col];
    }
    for (int t = threadIdx.x; t < 8192; t += blockDim.x) {
        int c = t & 3, lane_ = (t >> 2) & 31, kp = t >> 7;
        int k = 2 * kp + (c & 1);
        int col = lane_ + ((c & 2) ? 32 : 0);
        sW0[t] = W0[k * 64 + col];
    }
    if (threadIdx.x < 64) {
        seb1[threadIdx.x] = eb1[threadIdx.x];
        snb0[threadIdx.x] = b0[threadIdx.x];
        snb1[threadIdx.x] = b1[threadIdx.x];
    }
    __syncthreads();

    int lane = threadIdx.x & 31;
    int wid  = threadIdx.x >> 5;
    float* wbase = stage + wid * 640;
    float2* nP = reinterpret_cast<float2*>(wbase);
    const ulonglong2* E1v = reinterpret_cast<const ulonglong2*>(sE1);
    const ulonglong2* W0v = reinterpret_cast<const ulonglong2*>(sW0);
    const ulonglong2* W1v = reinterpret_cast<const ulonglong2*>(sW1);
    const unsigned long long* nU = reinterpret_cast<const unsigned long long*>(nP);
    float* hF = wbase;

    int wg = blockIdx.x * (blockDim.x >> 5) + wid;
    int ws = gridDim.x * (blockDim.x >> 5);
    for (int base = wg * 4; base < Nn; base += ws * 4) {
        float degf[4];
#pragma unroll
        for (int i = 0; i < 4; i++) {
            int n = base + i;
            if (n < Nn) {
                nP[lane * 5 + i]        = reinterpret_cast<const float2*>(g_h + n * 64)[lane];
                nP[(32 + lane) * 5 + i] = reinterpret_cast<const float2*>(g_agg + n * 64)[lane];
                degf[i] = (float)__ldg(&g_deg[n]);
            } else {
                nP[lane * 5 + i]        = make_float2(0.f, 0.f);
                nP[(32 + lane) * 5 + i] = make_float2(0.f, 0.f);
                degf[i] = 0.f;
            }
        }
        __syncwarp();

        // GEMM1: agg = Hsum·E1 + deg·eb1
        unsigned long long a0[4] = {0,0,0,0}, a1[4] = {0,0,0,0};
#pragma unroll 4
        for (int kp = 0; kp < 32; kp++) {
            ulonglong2 w = E1v[kp * 32 + lane];
#pragma unroll
            for (int i = 0; i < 4; i++) {
                unsigned long long v = nU[(32 + kp) * 5 + i];
                ffma2(a0[i], v, w.x); ffma2(a1[i], v, w.y);
            }
        }
        float e1a = seb1[lane], e1b = seb1[lane + 32];
        float aggL[4], aggH[4];
#pragma unroll
        for (int i = 0; i < 4; i++) {
            aggL[i] = usum(a0[i]) + degf[i] * e1a;
            aggH[i] = usum(a1[i]) + degf[i] * e1b;
        }
        __syncwarp();
        {
            int rL = ((32 + (lane >> 1)) * 5) * 2 + (lane & 1);
            int rH = ((48 + (lane >> 1)) * 5) * 2 + (lane & 1);
#pragma unroll
            for (int i = 0; i < 4; i++) {
                hF[rL + 2 * i] = aggL[i];
                hF[rH + 2 * i] = aggH[i];
            }
        }
        __syncwarp();

        // GEMM2: hidden = elu([h, agg]·W0 + b0)
        unsigned long long c0[4] = {0,0,0,0}, c1[4] = {0,0,0,0};
#pragma unroll 4
        for (int kp = 0; kp < 64; kp++) {
            ulonglong2 w = W0v[kp * 32 + lane];
#pragma unroll
            for (int i = 0; i < 4; i++) {
                unsigned long long v = nU[kp * 5 + i];
                ffma2(c0[i], v, w.x); ffma2(c1[i], v, w.y);
            }
        }
        float b0a = snb0[lane], b0b = snb0[lane + 32];
        float hL[4], hH[4];
#pragma unroll
        for (int i = 0; i < 4; i++) {
            hL[i] = elu_f(usum(c0[i]) + b0a);
            hH[i] = elu_f(usum(c1[i]) + b0b);
        }
        __syncwarp();
        {
            int rL = ((lane >> 1) * 5) * 2 + (lane & 1);
            int rH = ((16 + (lane >> 1)) * 5) * 2 + (lane & 1);
#pragma unroll
            for (int i = 0; i < 4; i++) {
                hF[rL + 2 * i] = hL[i];
                hF[rH + 2 * i] = hH[i];
            }
        }
        __syncwarp();

        // GEMM3: u = hidden·W1 + b1 ; h += u
        unsigned long long d0[4] = {0,0,0,0}, d1[4] = {0,0,0,0};
#pragma unroll 4
        for (int kp = 0; kp < 32; kp++) {
            ulonglong2 w = W1v[kp * 32 + lane];
#pragma unroll
            for (int i = 0; i < 4; i++) {
                unsigned long long v = nU[kp * 5 + i];
                ffma2(d0[i], v, w.x); ffma2(d1[i], v, w.y);
            }
        }
        float b1a = snb1[lane], b1b = snb1[lane + 32];
#pragma unroll
        for (int i = 0; i < 4; i++) {
            int n = base + i;
            if (n < Nn) {
                float old0 = g_h[n * 64 + lane];
                float old1 = g_h[n * 64 + 32 + lane];
                g_h[n * 64 + lane]      = old0 + usum(d0[i]) + b1a;
                g_h[n * 64 + 32 + lane] = old1 + usum(d1[i]) + b1b;
            }
        }
        __syncwarp();
    }
}

// ------------------------------------------------------------------ decoder (f32x2)
__global__ void decoder_kernel(const float* __restrict__ W0, const float* __restrict__ b0,
                               const float* __restrict__ W1, const float* __restrict__ b1,
                               float* __restrict__ out, int Nn) {
    extern __shared__ float sm[];
    float* sW0 = sm;            // 4096, kpair-packed
    float* sW1 = sm + 4096;     // 192 (row-major [64][3])
    float* sb0 = sm + 4288;     // 64
    float* sb1v = sm + 4352;    // 3 (+pad)
    float* stage = sm + 4356;   // 8 warps * 320

    for (int t = threadIdx.x; t < 4096; t += blockDim.x) {
        int c = t & 3, lane_ = (t >> 2) & 31, kp = t >> 7;
        int k = 2 * kp + (c & 1);
        int col = lane_ + ((c & 2) ? 32 : 0);
        sW0[t] = W0[k * 64 + col];
    }
    for (int t = threadIdx.x; t < 192; t += blockDim.x) sW1[t] = W1[t];
    if (threadIdx.x < 64) sb0[threadIdx.x] = b0[threadIdx.x];
    if (threadIdx.x < 3)  sb1v[threadIdx.x] = b1[threadIdx.x];
    __syncthreads();

    int lane = threadIdx.x & 31;
    int wid  = threadIdx.x >> 5;
    float* wbase = stage + wid * 320;
    float2* nP = reinterpret_cast<float2*>(wbase);
    const ulonglong2* W0v = reinterpret_cast<const ulonglong2*>(sW0);
    const unsigned long long* nU = reinterpret_cast<const unsigned long long*>(nP);
    const float2* H2 = reinterpret_cast<const float2*>(g_h);

    int wg = blockIdx.x * (blockDim.x >> 5) + wid;
    int ws = gridDim.x * (blockDim.x >> 5);
    for (int base = wg * 4; base < Nn; base += ws * 4) {
#pragma unroll
        for (int i = 0; i < 4; i++) {
            int n = base + i;
            nP[lane * 5 + i] = (n < Nn) ? __ldg(&H2[(size_t)n * 32 + lane]) : make_float2(0.f, 0.f);
        }
        __syncwarp();

        unsigned long long a0[4] = {0,0,0,0}, a1[4] = {0,0,0,0};
#pragma unroll 4
        for (int kp = 0; kp < 32; kp++) {
            ulonglong2 w = W0v[kp * 32 + lane];
#pragma unroll
            for (int i = 0; i < 4; i++) {
                unsigned long long v = nU[kp * 5 + i];
                ffma2(a0[i], v, w.x); ffma2(a1[i], v, w.y);
            }
        }
        float b0a = sb0[lane], b0b = sb0[lane + 32];
        float w1L0 = sW1[lane * 3 + 0], w1L1 = sW1[lane * 3 + 1], w1L2 = sW1[lane * 3 + 2];
        float w1H0 = sW1[(lane + 32) * 3 + 0], w1H1 = sW1[(lane + 32) * 3 + 1], w1H2 = sW1[(lane + 32) * 3 + 2];
#pragma unroll
        for (int i = 0; i < 4; i++) {
            int n = base + i;
            float hid0 = elu_f(usum(a0[i]) + b0a);
            float hid1 = elu_f(usum(a1[i]) + b0b);
            float p0 = hid0 * w1L0 + hid1 * w1H0;
            float p1 = hid0 * w1L1 + hid1 * w1H1;
            float p2 = hid0 * w1L2 + hid1 * w1H2;
#pragma unroll
            for (int off = 16; off; off >>= 1) {
                p0 += __shfl_xor_sync(~0u, p0, off);
                p1 += __shfl_xor_sync(~0u, p1, off);
                p2 += __shfl_xor_sync(~0u, p2, off);
            }
            if (lane == 0 && n < Nn) {
                out[n * 3 + 0] = p0 + sb1v[0];
                out[n * 3 + 1] = p1 + sb1v[1];
                out[n * 3 + 2] = p2 + sb1v[2];
            }
        }
        __syncwarp();
    }
}

// ------------------------------------------------------------------ launch
extern "C" void kernel_launch(void* const* d_in, const int* in_sizes, int n_in,
                              void* d_out, int out_size) {
    const float* x      = (const float*)d_in[0];
    const float* pos    = (const float*)d_in[1];
    const int*   ei     = (const int*)d_in[2];   // dtype auto-detected on device
    const float* enc_W0 = (const float*)d_in[3];
    const float* enc_b0 = (const float*)d_in[4];
    const float* enc_W1 = (const float*)d_in[5];
    const float* enc_b1 = (const float*)d_in[6];
    const float* dec_W0 = (const float*)d_in[7];
    const float* dec_b0 = (const float*)d_in[8];
    const float* dec_W1 = (const float*)d_in[9];
    const float* dec_b1 = (const float*)d_in[10];
    const float* eW0    = (const float*)d_in[11];
    const float* eb0    = (const float*)d_in[12];
    const float* eW1    = (const float*)d_in[13];
    const float* eb1    = (const float*)d_in[14];
    const float* nW0    = (const float*)d_in[15];
    const float* nb0    = (const float*)d_in[16];
    const float* nW1    = (const float*)d_in[17];
    const float* nb1    = (const float*)d_in[18];

    int Nn   = in_sizes[0] / 3;
    int Ecnt = in_sizes[2] / 2;
    if (Ecnt > EMAX) Ecnt = EMAX;
    float* out = (float*)d_out;

    const int ENCP_SMEM = (12864 + 8 * 320) * 4;   // 61,696 B
    const int PRE_SMEM  = (8448 + 8 * 320) * 4;    // 44,032 B
    const int NODE_SMEM = (16576 + 8 * 640) * 4;   // 86,784 B
    const int DEC_SMEM  = (4356 + 8 * 320) * 4;    // 27,664 B
    cudaFuncSetAttribute(enc_pre_kernel,    cudaFuncAttributeMaxDynamicSharedMemorySize, ENCP_SMEM);
    cudaFuncSetAttribute(pre_zero_kernel,   cudaFuncAttributeMaxDynamicSharedMemorySize, PRE_SMEM);
    cudaFuncSetAttribute(node_fused_kernel, cudaFuncAttributeMaxDynamicSharedMemorySize, NODE_SMEM);

    const int TPB = 256;
    const float* E0_0 = eW0;
    const float* E0_1 = eW0 + (size_t)195 * 64;

    probe_zero_kernel<<<148, TPB>>>(ei, Nn);                                        // 0
    convert_kernel<<<444, TPB>>>(ei, Ecnt, Nn);                                     // 1 (+zero agg l0)
    enc_pre_kernel<<<296, TPB, ENCP_SMEM>>>(x, pos, enc_W0, enc_b0, enc_W1, enc_b1,
                                            E0_0, eb0, Nn);                         // 2
    edge_scatter_kernel<<<592, TPB>>>(Ecnt);                                        // 3  ← profiled
    node_fused_kernel<<<296, TPB, NODE_SMEM>>>(eW1, eb1,
                                               nW0, nb0, nW1, nb1, Nn);             // 4
    pre_zero_kernel<<<296, TPB, PRE_SMEM>>>(E0_1, eb0 + 64, pos, Nn);               // 5
    edge_scatter_kernel<<<592, TPB>>>(Ecnt);                                        // 6
    node_fused_kernel<<<296, TPB, NODE_SMEM>>>(eW1 + (size_t)64 * 64, eb1 + 64,
                                               nW0 + (size_t)128 * 64, nb0 + 64,
                                               nW1 + (size_t)64 * 64,  nb1 + 64, Nn); // 7
    decoder_kernel<<<296, TPB, DEC_SMEM>>>(dec_W0, dec_b0, dec_W1, dec_b1, out, Nn);  // 8
}

// round 11
// speedup vs baseline: 2.0141x; 1.0684x over previous
#include <cuda_runtime.h>
#include <cuda_bf16.h>
#include <cuda_fp16.h>

#define NNODE 100000
#define EMAX  1600000
#define CDIM 64

__device__ __align__(16) float  g_h[NNODE * CDIM];
__device__ __align__(16) float  g_agg[NNODE * CDIM];
__device__ __align__(16) __half g_PAh[NNODE * CDIM];   // fp16: h·WA + pos·Wp
__device__ __align__(16) __half g_PBh[NNODE * CDIM];   // fp16: h·WB + b0 − pos·Wp
__device__ __align__(8)  int2   g_sd[EMAX];            // BYTE offsets into half arrays: (s*128, d*128)
__device__ __align__(16) float  g_W0c[2][8192];        // kpair-packed combined [W0h; eW1·W0a]
__device__ float g_v[2][64];                           // eb1·W0a
__device__ int   g_deg[NNODE];
__device__ int   g_mode;                               // 1 = int64 indices, 0 = int32

__device__ __forceinline__ float elu_f(float v) {
    return v > 0.f ? v : expm1f(v);
}
// fast elu for the edge hot path: MUFU-based
__device__ __forceinline__ float elu_fast(float v) {
    float e = __expf(v) - 1.f;
    return v > 0.f ? v : e;
}

// packed fp32x2 helpers (sm_100+)
__device__ __forceinline__ void ffma2(unsigned long long& d, unsigned long long a, unsigned long long b) {
    asm("fma.rn.f32x2 %0, %1, %2, %0;" : "+l"(d) : "l"(a), "l"(b));
}
__device__ __forceinline__ float usum(unsigned long long v) {
    float lo, hi;
    asm("mov.b64 {%0,%1}, %2;" : "=f"(lo), "=f"(hi) : "l"(v));
    return lo + hi;
}
__device__ __forceinline__ void red_add_v4(float* addr, float x, float y, float z, float w) {
    asm volatile("red.global.add.v4.f32 [%0], {%1, %2, %3, %4};"
                 :: "l"(addr), "f"(x), "f"(y), "f"(z), "f"(w) : "memory");
}

// ------------------------------------------------------------------ launch 0: probe dtype + zero deg
__global__ void probe_zero_kernel(const int* __restrict__ w, int Nn) {
    if (blockIdx.x == 0 && threadIdx.x == 0) {
        bool all_odd_zero = true;
        for (int i = 1; i < 64; i += 2)
            if (w[i] != 0) { all_odd_zero = false; break; }
        g_mode = all_odd_zero ? 1 : 0;
    }
    for (int i = blockIdx.x * blockDim.x + threadIdx.x; i < Nn; i += gridDim.x * blockDim.x)
        g_deg[i] = 0;
}

// ------------------------------------------------------------------ launch 1: convert indices + deg + zero agg (layer 0)
__global__ void convert_kernel(const int* __restrict__ w, int Ecnt, int Nn) {
    int mode = g_mode;
    for (int e = blockIdx.x * blockDim.x + threadIdx.x; e < Ecnt; e += gridDim.x * blockDim.x) {
        int s, d;
        if (mode) { s = w[2 * e]; d = w[2 * (Ecnt + e)]; }
        else      { s = w[e];     d = w[Ecnt + e]; }
        s = min(max(s, 0), NNODE - 1);
        d = min(max(d, 0), NNODE - 1);
        atomicAdd(&g_deg[d], 1);
        g_sd[e] = make_int2(s * 128, d * 128);   // byte offsets into [N,64] fp16 arrays
    }
    float4* p = reinterpret_cast<float4*>(g_agg);
    int n4 = Nn * 16;
    for (int i = blockIdx.x * blockDim.x + threadIdx.x; i < n4; i += gridDim.x * blockDim.x)
        p[i] = make_float4(0.f, 0.f, 0.f, 0.f);
}

// ------------------------------------------------------------------ launch 2: encoder + precompute(layer 0) fused
__global__ void enc_pre_kernel(const float* __restrict__ x, const float* __restrict__ pos,
                               const float* __restrict__ W0e, const float* __restrict__ b0e,
                               const float* __restrict__ W1e, const float* __restrict__ b1e,
                               const float* __restrict__ E0, const float* __restrict__ eb0,
                               int Nn) {
    extern __shared__ float sm[];
    float* sW1 = sm;             // 4096 kpair-packed (enc W1)
    float* sWA = sm + 4096;      // 4096
    float* sWB = sm + 8192;      // 4096
    float* sW0 = sm + 12288;     // 192 (enc W0)
    float* sWp = sm + 12480;     // 192 plain [3][64]
    float* sbe0 = sm + 12672;    // 64
    float* sbe1 = sm + 12736;    // 64
    float* sb0  = sm + 12800;    // 64 (edge b0)
    float* stage = sm + 12864;   // 8 warps * 320

    for (int t = threadIdx.x; t < 4096; t += blockDim.x) {
        int c = t & 3, lane_ = (t >> 2) & 31, kp = t >> 7;
        int k = 2 * kp + (c & 1);
        int col = lane_ + ((c & 2) ? 32 : 0);
        sW1[t] = W1e[k * 64 + col];
        float wC = E0[(128 + k) * 64 + col];
        sWA[t] = E0[k * 64 + col] + wC;
        sWB[t] = E0[(64 + k) * 64 + col] - wC;
    }
    for (int t = threadIdx.x; t < 192; t += blockDim.x) {
        sW0[t] = W0e[t];
        sWp[t] = E0[(192 + (t >> 6)) * 64 + (t & 63)];
    }
    if (threadIdx.x < 64) {
        sbe0[threadIdx.x] = b0e[threadIdx.x];
        sbe1[threadIdx.x] = b1e[threadIdx.x];
        sb0[threadIdx.x]  = eb0[threadIdx.x];
    }
    __syncthreads();

    int lane = threadIdx.x & 31;
    int wid  = threadIdx.x >> 5;
    float* wbase = stage + wid * 320;
    const ulonglong2* W1v = reinterpret_cast<const ulonglong2*>(sW1);
    const ulonglong2* WAv = reinterpret_cast<const ulonglong2*>(sWA);
    const ulonglong2* WBv = reinterpret_cast<const ulonglong2*>(sWB);
    const unsigned long long* nU = reinterpret_cast<const unsigned long long*>(wbase);
    float* hF = wbase;

    int rL = ((lane >> 1) * 5) * 2 + (lane & 1);
    int rH = ((16 + (lane >> 1)) * 5) * 2 + (lane & 1);

    int wg = blockIdx.x * (blockDim.x >> 5) + wid;
    int ws = gridDim.x * (blockDim.x >> 5);
    for (int base = wg * 4; base < Nn; base += ws * 4) {
        float p0v[4], p1v[4], p2v[4];
#pragma unroll
        for (int i = 0; i < 4; i++) {
            int n = base + i;
            float h0 = 0.f, h1 = 0.f;
            if (n < Nn) {
                float x0 = __ldg(&x[n * 3 + 0]), x1 = __ldg(&x[n * 3 + 1]), x2 = __ldg(&x[n * 3 + 2]);
                h0 = elu_f(x0 * sW0[lane]      + x1 * sW0[64 + lane]      + x2 * sW0[128 + lane]      + sbe0[lane]);
                h1 = elu_f(x0 * sW0[lane + 32] + x1 * sW0[64 + lane + 32] + x2 * sW0[128 + lane + 32] + sbe0[lane + 32]);
                p0v[i] = __ldg(&pos[n * 3 + 0]);
                p1v[i] = __ldg(&pos[n * 3 + 1]);
                p2v[i] = __ldg(&pos[n * 3 + 2]);
            } else { p0v[i] = p1v[i] = p2v[i] = 0.f; }
            hF[rL + 2 * i] = h0;
            hF[rH + 2 * i] = h1;
        }
        __syncwarp();

        // GEMM: h = hid·W1e + b1e
        unsigned long long a0[4] = {0,0,0,0}, a1[4] = {0,0,0,0};
#pragma unroll 4
        for (int kp = 0; kp < 32; kp++) {
            ulonglong2 w = W1v[kp * 32 + lane];
#pragma unroll
            for (int i = 0; i < 4; i++) {
                unsigned long long v = nU[kp * 5 + i];
                ffma2(a0[i], v, w.x); ffma2(a1[i], v, w.y);
            }
        }
        float b1a = sbe1[lane], b1b = sbe1[lane + 32];
        float hL[4], hH[4];
#pragma unroll
        for (int i = 0; i < 4; i++) {
            hL[i] = usum(a0[i]) + b1a;
            hH[i] = usum(a1[i]) + b1b;
            int n = base + i;
            if (n < Nn) {
                g_h[n * 64 + lane]      = hL[i];
                g_h[n * 64 + 32 + lane] = hH[i];
            }
        }
        __syncwarp();
#pragma unroll
        for (int i = 0; i < 4; i++) {
            hF[rL + 2 * i] = hL[i];
            hF[rH + 2 * i] = hH[i];
        }
        __syncwarp();

        // GEMMs: PA = h·WA + pos·Wp ; PB = h·WB + b0 − pos·Wp   (stored fp16)
        unsigned long long aA0[4] = {0,0,0,0}, aA1[4] = {0,0,0,0};
        unsigned long long aB0[4] = {0,0,0,0}, aB1[4] = {0,0,0,0};
#pragma unroll 4
        for (int kp = 0; kp < 32; kp++) {
            ulonglong2 wa = WAv[kp * 32 + lane];
            ulonglong2 wb = WBv[kp * 32 + lane];
#pragma unroll
            for (int i = 0; i < 4; i++) {
                unsigned long long v = nU[kp * 5 + i];
                ffma2(aA0[i], v, wa.x); ffma2(aA1[i], v, wa.y);
                ffma2(aB0[i], v, wb.x); ffma2(aB1[i], v, wb.y);
            }
        }
        float b0a = sb0[lane], b0b = sb0[lane + 32];
        float wpL0 = sWp[lane], wpL1 = sWp[64 + lane], wpL2 = sWp[128 + lane];
        float wpH0 = sWp[lane + 32], wpH1 = sWp[64 + lane + 32], wpH2 = sWp[128 + lane + 32];
#pragma unroll
        for (int i = 0; i < 4; i++) {
            int n = base + i;
            if (n < Nn) {
                float wpa = p0v[i] * wpL0 + p1v[i] * wpL1 + p2v[i] * wpL2;
                float wpb = p0v[i] * wpH0 + p1v[i] * wpH1 + p2v[i] * wpH2;
                g_PAh[n * 64 + lane]      = __float2half(usum(aA0[i]) + wpa);
                g_PAh[n * 64 + 32 + lane] = __float2half(usum(aA1[i]) + wpb);
                g_PBh[n * 64 + lane]      = __float2half(usum(aB0[i]) + b0a - wpa);
                g_PBh[n * 64 + 32 + lane] = __float2half(usum(aB1[i]) + b0b - wpb);
            }
        }
        __syncwarp();
    }
}

// ------------------------------------------------------------------ launch 3 (PROFILED): edge scatter (fp16 gathers)
// hidden = elu(PA[s] + PB[d]) → red.v4 into g_agg[d].
__global__ void edge_scatter_kernel(int Ecnt) {
    int lane = threadIdx.x & 31;
    int wid  = threadIdx.x >> 5;
    int slot = lane >> 4;            // 0/1: which edge of the pair
    int ch8  = (lane & 15) * 8;      // byte offset of 4-channel group in fp16 row

    const char* PAc = reinterpret_cast<const char*>(g_PAh) + ch8;
    const char* PBc = reinterpret_cast<const char*>(g_PBh) + ch8;
    char*       AGc = reinterpret_cast<char*>(g_agg) + ch8 * 2;

    int wg = blockIdx.x * (blockDim.x >> 5) + wid;
    int ws = gridDim.x * (blockDim.x >> 5);
    for (int base = wg * 8; base < Ecnt; base += ws * 8) {
        int2 ed[4];
        uint2 pa[4], pb[4];
#pragma unroll
        for (int p = 0; p < 4; p++) {
            int e = base + p * 2 + slot;
            ed[p] = (e < Ecnt) ? __ldg(&g_sd[e]) : make_int2(-1, -1);
        }
#pragma unroll
        for (int p = 0; p < 4; p++) {
            if (ed[p].x >= 0) {
                pa[p] = *reinterpret_cast<const uint2*>(PAc + ed[p].x);
                pb[p] = *reinterpret_cast<const uint2*>(PBc + ed[p].y);
            }
        }
#pragma unroll
        for (int p = 0; p < 4; p++) {
            if (ed[p].x >= 0) {
                float2 a0 = __half22float2(*reinterpret_cast<__half2*>(&pa[p].x));
                float2 a1 = __half22float2(*reinterpret_cast<__half2*>(&pa[p].y));
                float2 b0 = __half22float2(*reinterpret_cast<__half2*>(&pb[p].x));
                float2 b1 = __half22float2(*reinterpret_cast<__half2*>(&pb[p].y));
                float hx = elu_fast(a0.x + b0.x);
                float hy = elu_fast(a0.y + b0.y);
                float hz = elu_fast(a1.x + b1.x);
                float hw = elu_fast(a1.y + b1.y);
                red_add_v4(reinterpret_cast<float*>(AGc + ((size_t)ed[p].y << 1)), hx, hy, hz, hw);
            }
        }
    }
}

// ------------------------------------------------------------------ prep: fold eW1/eb1 into node W0 (both layers)
// W0c = [W0h ; eW1·W0a] (kpair-packed), v = eb1·W0a
__global__ void prep_kernel(const float* __restrict__ eW1, const float* __restrict__ eb1,
                            const float* __restrict__ nW0) {
    int l = blockIdx.x;
    const float* E1 = eW1 + (size_t)l * 4096;
    const float* B1 = eb1 + (size_t)l * 64;
    const float* W0 = nW0 + (size_t)l * 8192;
    __shared__ float sE1[4096];
    __shared__ float sW0a[4096];
    __shared__ float sB1[64];
    for (int t = threadIdx.x; t < 4096; t += blockDim.x) {
        sE1[t]  = E1[t];
        sW0a[t] = W0[4096 + t];
    }
    if (threadIdx.x < 64) sB1[threadIdx.x] = B1[threadIdx.x];
    __syncthreads();

    if (threadIdx.x < 64) {
        float acc = 0.f;
        for (int m = 0; m < 64; m++) acc += sB1[m] * sW0a[m * 64 + threadIdx.x];
        g_v[l][threadIdx.x] = acc;
    }
    for (int t = threadIdx.x; t < 8192; t += blockDim.x) {
        int c = t & 3, lane_ = (t >> 2) & 31, kp = t >> 7;
        int k = 2 * kp + (c & 1);
        int col = lane_ + ((c & 2) ? 32 : 0);
        float val;
        if (k < 64) {
            val = W0[k * 64 + col];
        } else {
            int kk = k - 64;
            float acc = 0.f;
            for (int m = 0; m < 64; m++) acc += sE1[kk * 64 + m] * sW0a[m * 64 + col];
            val = acc;
        }
        g_W0c[l][t] = val;
    }
}

// ------------------------------------------------------------------ precompute (layer 1) + zero agg
__global__ void pre_zero_kernel(const float* __restrict__ E0, const float* __restrict__ eb0,
                                const float* __restrict__ pos, int Nn) {
    extern __shared__ float sm[];
    float* sWA = sm;            // 4096
    float* sWB = sm + 4096;     // 4096
    float* sWp = sm + 8192;     // 192
    float* sb0 = sm + 8384;     // 64
    float* stage = sm + 8448;   // 8 warps * 320

    for (int t = threadIdx.x; t < 4096; t += blockDim.x) {
        int c = t & 3, lane_ = (t >> 2) & 31, kp = t >> 7;
        int k = 2 * kp + (c & 1);
        int col = lane_ + ((c & 2) ? 32 : 0);
        float wC = E0[(128 + k) * 64 + col];
        sWA[t] = E0[k * 64 + col] + wC;
        sWB[t] = E0[(64 + k) * 64 + col] - wC;
    }
    for (int t = threadIdx.x; t < 192; t += blockDim.x)
        sWp[t] = E0[(192 + (t >> 6)) * 64 + (t & 63)];
    if (threadIdx.x < 64) sb0[threadIdx.x] = eb0[threadIdx.x];
    __syncthreads();

    int lane = threadIdx.x & 31;
    int wid  = threadIdx.x >> 5;
    float* wbase = stage + wid * 320;
    float2* nP = reinterpret_cast<float2*>(wbase);
    const ulonglong2* WAv = reinterpret_cast<const ulonglong2*>(sWA);
    const ulonglong2* WBv = reinterpret_cast<const ulonglong2*>(sWB);
    const unsigned long long* nU = reinterpret_cast<const unsigned long long*>(nP);

    int wg = blockIdx.x * (blockDim.x >> 5) + wid;
    int ws = gridDim.x * (blockDim.x >> 5);
    for (int base = wg * 4; base < Nn; base += ws * 4) {
        float p0v[4], p1v[4], p2v[4];
#pragma unroll
        for (int i = 0; i < 4; i++) {
            int n = base + i;
            if (n < Nn) {
                nP[lane * 5 + i] = reinterpret_cast<const float2*>(g_h + n * 64)[lane];
                p0v[i] = __ldg(&pos[n * 3 + 0]);
                p1v[i] = __ldg(&pos[n * 3 + 1]);
                p2v[i] = __ldg(&pos[n * 3 + 2]);
                reinterpret_cast<float2*>(g_agg + n * 64)[lane] = make_float2(0.f, 0.f);
            } else {
                nP[lane * 5 + i] = make_float2(0.f, 0.f);
                p0v[i] = p1v[i] = p2v[i] = 0.f;
            }
        }
        __syncwarp();

        unsigned long long aA0[4] = {0,0,0,0}, aA1[4] = {0,0,0,0};
        unsigned long long aB0[4] = {0,0,0,0}, aB1[4] = {0,0,0,0};
#pragma unroll 4
        for (int kp = 0; kp < 32; kp++) {
            ulonglong2 wa = WAv[kp * 32 + lane];
            ulonglong2 wb = WBv[kp * 32 + lane];
#pragma unroll
            for (int i = 0; i < 4; i++) {
                unsigned long long v = nU[kp * 5 + i];
                ffma2(aA0[i], v, wa.x); ffma2(aA1[i], v, wa.y);
                ffma2(aB0[i], v, wb.x); ffma2(aB1[i], v, wb.y);
            }
        }
        float b0a = sb0[lane], b0b = sb0[lane + 32];
        float wpL0 = sWp[lane], wpL1 = sWp[64 + lane], wpL2 = sWp[128 + lane];
        float wpH0 = sWp[lane + 32], wpH1 = sWp[64 + lane + 32], wpH2 = sWp[128 + lane + 32];
#pragma unroll
        for (int i = 0; i < 4; i++) {
            int n = base + i;
            if (n < Nn) {
                float wpa = p0v[i] * wpL0 + p1v[i] * wpL1 + p2v[i] * wpL2;
                float wpb = p0v[i] * wpH0 + p1v[i] * wpH1 + p2v[i] * wpH2;
                g_PAh[n * 64 + lane]      = __float2half(usum(aA0[i]) + wpa);
                g_PAh[n * 64 + 32 + lane] = __float2half(usum(aA1[i]) + wpb);
                g_PBh[n * 64 + lane]      = __float2half(usum(aB0[i]) + b0a - wpa);
                g_PBh[n * 64 + 32 + lane] = __float2half(usum(aB1[i]) + b0b - wpb);
            }
        }
        __syncwarp();
    }
}

// ------------------------------------------------------------------ fused node update (E1 folded):
// hidden = elu(h·W0h + Hsum·W0E + deg·v + b0) ; u = hidden·W1 + b1 ; h += u
__global__ void node_fused_kernel(const float* __restrict__ W0c, const float* __restrict__ vv,
                                  const float* __restrict__ W1, const float* __restrict__ b0,
                                  const float* __restrict__ b1, int Nn) {
    extern __shared__ float sm[];
    float* sW0 = sm;             // 8192 (kpair-packed combined, direct copy)
    float* sW1 = sm + 8192;      // 4096
    float* sv  = sm + 12288;     // 64
    float* snb0 = sm + 12352;    // 64
    float* snb1 = sm + 12416;    // 64
    float* stage = sm + 12480;   // 8 warps * 640

    for (int t = threadIdx.x; t < 8192; t += blockDim.x) sW0[t] = W0c[t];
    for (int t = threadIdx.x; t < 4096; t += blockDim.x) {
        int c = t & 3, lane_ = (t >> 2) & 31, kp = t >> 7;
        int k = 2 * kp + (c & 1);
        int col = lane_ + ((c & 2) ? 32 : 0);
        sW1[t] = W1[k * 64 + col];
    }
    if (threadIdx.x < 64) {
        sv[threadIdx.x]   = vv[threadIdx.x];
        snb0[threadIdx.x] = b0[threadIdx.x];
        snb1[threadIdx.x] = b1[threadIdx.x];
    }
    __syncthreads();

    int lane = threadIdx.x & 31;
    int wid  = threadIdx.x >> 5;
    float* wbase = stage + wid * 640;
    float2* nP = reinterpret_cast<float2*>(wbase);
    const ulonglong2* W0v = reinterpret_cast<const ulonglong2*>(sW0);
    const ulonglong2* W1v = reinterpret_cast<const ulonglong2*>(sW1);
    const unsigned long long* nU = reinterpret_cast<const unsigned long long*>(nP);
    float* hF = wbase;

    int wg = blockIdx.x * (blockDim.x >> 5) + wid;
    int ws = gridDim.x * (blockDim.x >> 5);
    for (int base = wg * 4; base < Nn; base += ws * 4) {
        float degf[4];
#pragma unroll
        for (int i = 0; i < 4; i++) {
            int n = base + i;
            if (n < Nn) {
                nP[lane * 5 + i]        = reinterpret_cast<const float2*>(g_h + n * 64)[lane];
                nP[(32 + lane) * 5 + i] = reinterpret_cast<const float2*>(g_agg + n * 64)[lane];
                degf[i] = (float)__ldg(&g_deg[n]);
            } else {
                nP[lane * 5 + i]        = make_float2(0.f, 0.f);
                nP[(32 + lane) * 5 + i] = make_float2(0.f, 0.f);
                degf[i] = 0.f;
            }
        }
        __syncwarp();

        // GEMM: hidden = elu([h, Hsum]·W0c + deg·v + b0)
        unsigned long long c0[4] = {0,0,0,0}, c1[4] = {0,0,0,0};
#pragma unroll 4
        for (int kp = 0; kp < 64; kp++) {
            ulonglong2 w = W0v[kp * 32 + lane];
#pragma unroll
            for (int i = 0; i < 4; i++) {
                unsigned long long v = nU[kp * 5 + i];
                ffma2(c0[i], v, w.x); ffma2(c1[i], v, w.y);
            }
        }
        float b0a = snb0[lane], b0b = snb0[lane + 32];
        float svL = sv[lane],   svH = sv[lane + 32];
        float hL[4], hH[4];
#pragma unroll
        for (int i = 0; i < 4; i++) {
            hL[i] = elu_f(usum(c0[i]) + degf[i] * svL + b0a);
            hH[i] = elu_f(usum(c1[i]) + degf[i] * svH + b0b);
        }
        __syncwarp();
        {
            int rL = ((lane >> 1) * 5) * 2 + (lane & 1);
            int rH = ((16 + (lane >> 1)) * 5) * 2 + (lane & 1);
#pragma unroll
            for (int i = 0; i < 4; i++) {
                hF[rL + 2 * i] = hL[i];
                hF[rH + 2 * i] = hH[i];
            }
        }
        __syncwarp();

        // GEMM: u = hidden·W1 + b1 ; h += u
        unsigned long long d0[4] = {0,0,0,0}, d1[4] = {0,0,0,0};
#pragma unroll 4
        for (int kp = 0; kp < 32; kp++) {
            ulonglong2 w = W1v[kp * 32 + lane];
#pragma unroll
            for (int i = 0; i < 4; i++) {
                unsigned long long v = nU[kp * 5 + i];
                ffma2(d0[i], v, w.x); ffma2(d1[i], v, w.y);
            }
        }
        float b1a = snb1[lane], b1b = snb1[lane + 32];
#pragma unroll
        for (int i = 0; i < 4; i++) {
            int n = base + i;
            if (n < Nn) {
                float old0 = g_h[n * 64 + lane];
                float old1 = g_h[n * 64 + 32 + lane];
                g_h[n * 64 + lane]      = old0 + usum(d0[i]) + b1a;
                g_h[n * 64 + 32 + lane] = old1 + usum(d1[i]) + b1b;
            }
        }
        __syncwarp();
    }
}

// ------------------------------------------------------------------ decoder (f32x2)
__global__ void decoder_kernel(const float* __restrict__ W0, const float* __restrict__ b0,
                               const float* __restrict__ W1, const float* __restrict__ b1,
                               float* __restrict__ out, int Nn) {
    extern __shared__ float sm[];
    float* sW0 = sm;            // 4096, kpair-packed
    float* sW1 = sm + 4096;     // 192 (row-major [64][3])
    float* sb0 = sm + 4288;     // 64
    float* sb1v = sm + 4352;    // 3 (+pad)
    float* stage = sm + 4356;   // 8 warps * 320

    for (int t = threadIdx.x; t < 4096; t += blockDim.x) {
        int c = t & 3, lane_ = (t >> 2) & 31, kp = t >> 7;
        int k = 2 * kp + (c & 1);
        int col = lane_ + ((c & 2) ? 32 : 0);
        sW0[t] = W0[k * 64 + col];
    }
    for (int t = threadIdx.x; t < 192; t += blockDim.x) sW1[t] = W1[t];
    if (threadIdx.x < 64) sb0[threadIdx.x] = b0[threadIdx.x];
    if (threadIdx.x < 3)  sb1v[threadIdx.x] = b1[threadIdx.x];
    __syncthreads();

    int lane = threadIdx.x & 31;
    int wid  = threadIdx.x >> 5;
    float* wbase = stage + wid * 320;
    float2* nP = reinterpret_cast<float2*>(wbase);
    const ulonglong2* W0v = reinterpret_cast<const ulonglong2*>(sW0);
    const unsigned long long* nU = reinterpret_cast<const unsigned long long*>(nP);
    const float2* H2 = reinterpret_cast<const float2*>(g_h);

    int wg = blockIdx.x * (blockDim.x >> 5) + wid;
    int ws = gridDim.x * (blockDim.x >> 5);
    for (int base = wg * 4; base < Nn; base += ws * 4) {
#pragma unroll
        for (int i = 0; i < 4; i++) {
            int n = base + i;
            nP[lane * 5 + i] = (n < Nn) ? __ldg(&H2[(size_t)n * 32 + lane]) : make_float2(0.f, 0.f);
        }
        __syncwarp();

        unsigned long long a0[4] = {0,0,0,0}, a1[4] = {0,0,0,0};
#pragma unroll 4
        for (int kp = 0; kp < 32; kp++) {
            ulonglong2 w = W0v[kp * 32 + lane];
#pragma unroll
            for (int i = 0; i < 4; i++) {
                unsigned long long v = nU[kp * 5 + i];
                ffma2(a0[i], v, w.x); ffma2(a1[i], v, w.y);
            }
        }
        float b0a = sb0[lane], b0b = sb0[lane + 32];
        float w1L0 = sW1[lane * 3 + 0], w1L1 = sW1[lane * 3 + 1], w1L2 = sW1[lane * 3 + 2];
        float w1H0 = sW1[(lane + 32) * 3 + 0], w1H1 = sW1[(lane + 32) * 3 + 1], w1H2 = sW1[(lane + 32) * 3 + 2];
#pragma unroll
        for (int i = 0; i < 4; i++) {
            int n = base + i;
            float hid0 = elu_f(usum(a0[i]) + b0a);
            float hid1 = elu_f(usum(a1[i]) + b0b);
            float p0 = hid0 * w1L0 + hid1 * w1H0;
            float p1 = hid0 * w1L1 + hid1 * w1H1;
            float p2 = hid0 * w1L2 + hid1 * w1H2;
#pragma unroll
            for (int off = 16; off; off >>= 1) {
                p0 += __shfl_xor_sync(~0u, p0, off);
                p1 += __shfl_xor_sync(~0u, p1, off);
                p2 += __shfl_xor_sync(~0u, p2, off);
            }
            if (lane == 0 && n < Nn) {
                out[n * 3 + 0] = p0 + sb1v[0];
                out[n * 3 + 1] = p1 + sb1v[1];
                out[n * 3 + 2] = p2 + sb1v[2];
            }
        }
        __syncwarp();
    }
}

// ------------------------------------------------------------------ launch
extern "C" void kernel_launch(void* const* d_in, const int* in_sizes, int n_in,
                              void* d_out, int out_size) {
    const float* x      = (const float*)d_in[0];
    const float* pos    = (const float*)d_in[1];
    const int*   ei     = (const int*)d_in[2];   // dtype auto-detected on device
    const float* enc_W0 = (const float*)d_in[3];
    const float* enc_b0 = (const float*)d_in[4];
    const float* enc_W1 = (const float*)d_in[5];
    const float* enc_b1 = (const float*)d_in[6];
    const float* dec_W0 = (const float*)d_in[7];
    const float* dec_b0 = (const float*)d_in[8];
    const float* dec_W1 = (const float*)d_in[9];
    const float* dec_b1 = (const float*)d_in[10];
    const float* eW0    = (const float*)d_in[11];
    const float* eb0    = (const float*)d_in[12];
    const float* eW1    = (const float*)d_in[13];
    const float* eb1    = (const float*)d_in[14];
    const float* nW0    = (const float*)d_in[15];
    const float* nb0    = (const float*)d_in[16];
    const float* nW1    = (const float*)d_in[17];
    const float* nb1    = (const float*)d_in[18];

    int Nn   = in_sizes[0] / 3;
    int Ecnt = in_sizes[2] / 2;
    if (Ecnt > EMAX) Ecnt = EMAX;
    float* out = (float*)d_out;

    const int ENCP_SMEM = (12864 + 8 * 320) * 4;   // 61,696 B
    const int PRE_SMEM  = (8448 + 8 * 320) * 4;    // 44,032 B
    const int NODE_SMEM = (12480 + 8 * 640) * 4;   // 70,400 B
    const int DEC_SMEM  = (4356 + 8 * 320) * 4;    // 27,664 B
    cudaFuncSetAttribute(enc_pre_kernel,    cudaFuncAttributeMaxDynamicSharedMemorySize, ENCP_SMEM);
    cudaFuncSetAttribute(pre_zero_kernel,   cudaFuncAttributeMaxDynamicSharedMemorySize, PRE_SMEM);
    cudaFuncSetAttribute(node_fused_kernel, cudaFuncAttributeMaxDynamicSharedMemorySize, NODE_SMEM);

    const int TPB = 256;
    const float* E0_0 = eW0;
    const float* E0_1 = eW0 + (size_t)195 * 64;
    const float* W0c0 = &((const float*)nullptr)[0];  // placeholder (unused)

    probe_zero_kernel<<<148, TPB>>>(ei, Nn);                                          // 0
    convert_kernel<<<444, TPB>>>(ei, Ecnt, Nn);                                       // 1 (+zero agg l0)
    enc_pre_kernel<<<296, TPB, ENCP_SMEM>>>(x, pos, enc_W0, enc_b0, enc_W1, enc_b1,
                                            E0_0, eb0, Nn);                           // 2
    edge_scatter_kernel<<<592, TPB>>>(Ecnt);                                          // 3  ← profiled
    prep_kernel<<<2, 256>>>(eW1, eb1, nW0);                                           // 4 (both layers)
    {
        float* w0c; float* vv;
        cudaGetSymbolAddress((void**)&w0c, g_W0c);
        cudaGetSymbolAddress((void**)&vv,  g_v);
        node_fused_kernel<<<296, TPB, NODE_SMEM>>>(w0c, vv,
                                                   nW1, nb0, nb1, Nn);                // 5 (layer 0)
        pre_zero_kernel<<<296, TPB, PRE_SMEM>>>(E0_1, eb0 + 64, pos, Nn);             // 6
        edge_scatter_kernel<<<592, TPB>>>(Ecnt);                                      // 7
        node_fused_kernel<<<296, TPB, NODE_SMEM>>>(w0c + 8192, vv + 64,
                                                   nW1 + (size_t)64 * 64, nb0 + 64,
                                                   nb1 + 64, Nn);                     // 8 (layer 1)
    }
    decoder_kernel<<<296, TPB, DEC_SMEM>>>(dec_W0, dec_b0, dec_W1, dec_b1, out, Nn);  // 9
}

// round 12
// speedup vs baseline: 2.0841x; 1.0347x over previous
#include <cuda_runtime.h>
#include <cuda_bf16.h>
#include <cuda_fp16.h>

#define NNODE 100000
#define EMAX  1600000
#define CDIM 64

__device__ __align__(16) float  g_h[NNODE * CDIM];
__device__ __align__(16) float  g_agg[NNODE * CDIM];
__device__ __align__(16) __half g_PAh[NNODE * CDIM];   // fp16: h·WA + pos·Wp
__device__ __align__(16) __half g_PBh[NNODE * CDIM];   // fp16: h·WB + b0 − pos·Wp
__device__ __align__(8)  int2   g_sd[EMAX];            // BYTE offsets into half arrays: (s*128, d*128)
__device__ __align__(16) float  g_W0c[2][8192];        // kpair-packed combined [W0h; eW1·W0a]
__device__ float g_v[2][64];                           // eb1·W0a
__device__ int   g_deg[NNODE];
__device__ int   g_mode;                               // 1 = int64 indices, 0 = int32

__device__ __forceinline__ float elu_f(float v) {
    return v > 0.f ? v : expm1f(v);
}
__device__ __forceinline__ float elu_fast(float v) {
    float e = __expf(v) - 1.f;
    return v > 0.f ? v : e;
}

// packed fp32x2 helpers (sm_100+)
__device__ __forceinline__ void ffma2(unsigned long long& d, unsigned long long a, unsigned long long b) {
    asm("fma.rn.f32x2 %0, %1, %2, %0;" : "+l"(d) : "l"(a), "l"(b));
}
__device__ __forceinline__ float usum(unsigned long long v) {
    float lo, hi;
    asm("mov.b64 {%0,%1}, %2;" : "=f"(lo), "=f"(hi) : "l"(v));
    return lo + hi;
}
__device__ __forceinline__ void red_add_v4(float* addr, float x, float y, float z, float w) {
    asm volatile("red.global.add.v4.f32 [%0], {%1, %2, %3, %4};"
                 :: "l"(addr), "f"(x), "f"(y), "f"(z), "f"(w) : "memory");
}

// ------------------------------------------------------------------ launch 0: probe dtype + zero deg
__global__ void probe_zero_kernel(const int* __restrict__ w, int Nn) {
    if (blockIdx.x == 0 && threadIdx.x == 0) {
        bool all_odd_zero = true;
        for (int i = 1; i < 64; i += 2)
            if (w[i] != 0) { all_odd_zero = false; break; }
        g_mode = all_odd_zero ? 1 : 0;
    }
    for (int i = blockIdx.x * blockDim.x + threadIdx.x; i < Nn; i += gridDim.x * blockDim.x)
        g_deg[i] = 0;
}

// ------------------------------------------------------------------ launch 1: convert indices + deg + zero agg (layer 0)
__global__ void convert_kernel(const int* __restrict__ w, int Ecnt, int Nn) {
    int mode = g_mode;
    for (int e = blockIdx.x * blockDim.x + threadIdx.x; e < Ecnt; e += gridDim.x * blockDim.x) {
        int s, d;
        if (mode) { s = w[2 * e]; d = w[2 * (Ecnt + e)]; }
        else      { s = w[e];     d = w[Ecnt + e]; }
        s = min(max(s, 0), NNODE - 1);
        d = min(max(d, 0), NNODE - 1);
        atomicAdd(&g_deg[d], 1);
        g_sd[e] = make_int2(s * 128, d * 128);
    }
    float4* p = reinterpret_cast<float4*>(g_agg);
    int n4 = Nn * 16;
    for (int i = blockIdx.x * blockDim.x + threadIdx.x; i < n4; i += gridDim.x * blockDim.x)
        p[i] = make_float4(0.f, 0.f, 0.f, 0.f);
}

// ------------------------------------------------------------------ launch 2: encoder + precompute(layer 0) fused
__global__ void enc_pre_kernel(const float* __restrict__ x, const float* __restrict__ pos,
                               const float* __restrict__ W0e, const float* __restrict__ b0e,
                               const float* __restrict__ W1e, const float* __restrict__ b1e,
                               const float* __restrict__ E0, const float* __restrict__ eb0,
                               int Nn) {
    extern __shared__ float sm[];
    float* sW1 = sm;             // 4096 kpair-packed (enc W1)
    float* sWA = sm + 4096;      // 4096
    float* sWB = sm + 8192;      // 4096
    float* sW0 = sm + 12288;     // 192 (enc W0)
    float* sWp = sm + 12480;     // 192
    float* sbe0 = sm + 12672;    // 64
    float* sbe1 = sm + 12736;    // 64
    float* sb0  = sm + 12800;    // 64 (edge b0)
    float* stage = sm + 12864;   // 8 warps * 320

    for (int t = threadIdx.x; t < 4096; t += blockDim.x) {
        int c = t & 3, lane_ = (t >> 2) & 31, kp = t >> 7;
        int k = 2 * kp + (c & 1);
        int col = lane_ + ((c & 2) ? 32 : 0);
        sW1[t] = W1e[k * 64 + col];
        float wC = E0[(128 + k) * 64 + col];
        sWA[t] = E0[k * 64 + col] + wC;
        sWB[t] = E0[(64 + k) * 64 + col] - wC;
    }
    for (int t = threadIdx.x; t < 192; t += blockDim.x) {
        sW0[t] = W0e[t];
        sWp[t] = E0[(192 + (t >> 6)) * 64 + (t & 63)];
    }
    if (threadIdx.x < 64) {
        sbe0[threadIdx.x] = b0e[threadIdx.x];
        sbe1[threadIdx.x] = b1e[threadIdx.x];
        sb0[threadIdx.x]  = eb0[threadIdx.x];
    }
    __syncthreads();

    int lane = threadIdx.x & 31;
    int wid  = threadIdx.x >> 5;
    float* wbase = stage + wid * 320;
    const ulonglong2* W1v = reinterpret_cast<const ulonglong2*>(sW1);
    const ulonglong2* WAv = reinterpret_cast<const ulonglong2*>(sWA);
    const ulonglong2* WBv = reinterpret_cast<const ulonglong2*>(sWB);
    const unsigned long long* nU = reinterpret_cast<const unsigned long long*>(wbase);
    float* hF = wbase;

    int rL = ((lane >> 1) * 5) * 2 + (lane & 1);
    int rH = ((16 + (lane >> 1)) * 5) * 2 + (lane & 1);

    int wg = blockIdx.x * (blockDim.x >> 5) + wid;
    int ws = gridDim.x * (blockDim.x >> 5);
    for (int base = wg * 4; base < Nn; base += ws * 4) {
        float p0v[4], p1v[4], p2v[4];
#pragma unroll
        for (int i = 0; i < 4; i++) {
            int n = base + i;
            float h0 = 0.f, h1 = 0.f;
            if (n < Nn) {
                float x0 = __ldg(&x[n * 3 + 0]), x1 = __ldg(&x[n * 3 + 1]), x2 = __ldg(&x[n * 3 + 2]);
                h0 = elu_f(x0 * sW0[lane]      + x1 * sW0[64 + lane]      + x2 * sW0[128 + lane]      + sbe0[lane]);
                h1 = elu_f(x0 * sW0[lane + 32] + x1 * sW0[64 + lane + 32] + x2 * sW0[128 + lane + 32] + sbe0[lane + 32]);
                p0v[i] = __ldg(&pos[n * 3 + 0]);
                p1v[i] = __ldg(&pos[n * 3 + 1]);
                p2v[i] = __ldg(&pos[n * 3 + 2]);
            } else { p0v[i] = p1v[i] = p2v[i] = 0.f; }
            hF[rL + 2 * i] = h0;
            hF[rH + 2 * i] = h1;
        }
        __syncwarp();

        unsigned long long a0[4] = {0,0,0,0}, a1[4] = {0,0,0,0};
#pragma unroll 4
        for (int kp = 0; kp < 32; kp++) {
            ulonglong2 w = W1v[kp * 32 + lane];
#pragma unroll
            for (int i = 0; i < 4; i++) {
                unsigned long long v = nU[kp * 5 + i];
                ffma2(a0[i], v, w.x); ffma2(a1[i], v, w.y);
            }
        }
        float b1a = sbe1[lane], b1b = sbe1[lane + 32];
        float hL[4], hH[4];
#pragma unroll
        for (int i = 0; i < 4; i++) {
            hL[i] = usum(a0[i]) + b1a;
            hH[i] = usum(a1[i]) + b1b;
            int n = base + i;
            if (n < Nn) {
                g_h[n * 64 + lane]      = hL[i];
                g_h[n * 64 + 32 + lane] = hH[i];
            }
        }
        __syncwarp();
#pragma unroll
        for (int i = 0; i < 4; i++) {
            hF[rL + 2 * i] = hL[i];
            hF[rH + 2 * i] = hH[i];
        }
        __syncwarp();

        unsigned long long aA0[4] = {0,0,0,0}, aA1[4] = {0,0,0,0};
        unsigned long long aB0[4] = {0,0,0,0}, aB1[4] = {0,0,0,0};
#pragma unroll 4
        for (int kp = 0; kp < 32; kp++) {
            ulonglong2 wa = WAv[kp * 32 + lane];
            ulonglong2 wb = WBv[kp * 32 + lane];
#pragma unroll
            for (int i = 0; i < 4; i++) {
                unsigned long long v = nU[kp * 5 + i];
                ffma2(aA0[i], v, wa.x); ffma2(aA1[i], v, wa.y);
                ffma2(aB0[i], v, wb.x); ffma2(aB1[i], v, wb.y);
            }
        }
        float b0a = sb0[lane], b0b = sb0[lane + 32];
        float wpL0 = sWp[lane], wpL1 = sWp[64 + lane], wpL2 = sWp[128 + lane];
        float wpH0 = sWp[lane + 32], wpH1 = sWp[64 + lane + 32], wpH2 = sWp[128 + lane + 32];
#pragma unroll
        for (int i = 0; i < 4; i++) {
            int n = base + i;
            if (n < Nn) {
                float wpa = p0v[i] * wpL0 + p1v[i] * wpL1 + p2v[i] * wpL2;
                float wpb = p0v[i] * wpH0 + p1v[i] * wpH1 + p2v[i] * wpH2;
                g_PAh[n * 64 + lane]      = __float2half(usum(aA0[i]) + wpa);
                g_PAh[n * 64 + 32 + lane] = __float2half(usum(aA1[i]) + wpb);
                g_PBh[n * 64 + lane]      = __float2half(usum(aB0[i]) + b0a - wpa);
                g_PBh[n * 64 + 32 + lane] = __float2half(usum(aB1[i]) + b0b - wpb);
            }
        }
        __syncwarp();
    }
}

// ------------------------------------------------------------------ launch 3 (PROFILED): edge scatter (fp16 gathers)
__global__ void edge_scatter_kernel(int Ecnt) {
    int lane = threadIdx.x & 31;
    int wid  = threadIdx.x >> 5;
    int slot = lane >> 4;
    int ch8  = (lane & 15) * 8;

    const char* PAc = reinterpret_cast<const char*>(g_PAh) + ch8;
    const char* PBc = reinterpret_cast<const char*>(g_PBh) + ch8;
    char*       AGc = reinterpret_cast<char*>(g_agg) + ch8 * 2;

    int wg = blockIdx.x * (blockDim.x >> 5) + wid;
    int ws = gridDim.x * (blockDim.x >> 5);
    for (int base = wg * 8; base < Ecnt; base += ws * 8) {
        int2 ed[4];
        uint2 pa[4], pb[4];
#pragma unroll
        for (int p = 0; p < 4; p++) {
            int e = base + p * 2 + slot;
            ed[p] = (e < Ecnt) ? __ldg(&g_sd[e]) : make_int2(-1, -1);
        }
#pragma unroll
        for (int p = 0; p < 4; p++) {
            if (ed[p].x >= 0) {
                pa[p] = *reinterpret_cast<const uint2*>(PAc + ed[p].x);
                pb[p] = *reinterpret_cast<const uint2*>(PBc + ed[p].y);
            }
        }
#pragma unroll
        for (int p = 0; p < 4; p++) {
            if (ed[p].x >= 0) {
                float2 a0 = __half22float2(*reinterpret_cast<__half2*>(&pa[p].x));
                float2 a1 = __half22float2(*reinterpret_cast<__half2*>(&pa[p].y));
                float2 b0 = __half22float2(*reinterpret_cast<__half2*>(&pb[p].x));
                float2 b1 = __half22float2(*reinterpret_cast<__half2*>(&pb[p].y));
                float hx = elu_fast(a0.x + b0.x);
                float hy = elu_fast(a0.y + b0.y);
                float hz = elu_fast(a1.x + b1.x);
                float hw = elu_fast(a1.y + b1.y);
                red_add_v4(reinterpret_cast<float*>(AGc + ((size_t)ed[p].y << 1)), hx, hy, hz, hw);
            }
        }
    }
}

// ------------------------------------------------------------------ prep: fold eW1/eb1 into node W0 (both layers)
__global__ void prep_kernel(const float* __restrict__ eW1, const float* __restrict__ eb1,
                            const float* __restrict__ nW0) {
    int l = blockIdx.x;
    const float* E1 = eW1 + (size_t)l * 4096;
    const float* B1 = eb1 + (size_t)l * 64;
    const float* W0 = nW0 + (size_t)l * 8192;
    __shared__ float sE1[4096];
    __shared__ float sW0a[4096];
    __shared__ float sB1[64];
    for (int t = threadIdx.x; t < 4096; t += blockDim.x) {
        sE1[t]  = E1[t];
        sW0a[t] = W0[4096 + t];
    }
    if (threadIdx.x < 64) sB1[threadIdx.x] = B1[threadIdx.x];
    __syncthreads();

    if (threadIdx.x < 64) {
        float acc = 0.f;
        for (int m = 0; m < 64; m++) acc += sB1[m] * sW0a[m * 64 + threadIdx.x];
        g_v[l][threadIdx.x] = acc;
    }
    for (int t = threadIdx.x; t < 8192; t += blockDim.x) {
        int c = t & 3, lane_ = (t >> 2) & 31, kp = t >> 7;
        int k = 2 * kp + (c & 1);
        int col = lane_ + ((c & 2) ? 32 : 0);
        float val;
        if (k < 64) {
            val = W0[k * 64 + col];
        } else {
            int kk = k - 64;
            float acc = 0.f;
            for (int m = 0; m < 64; m++) acc += sE1[kk * 64 + m] * sW0a[m * 64 + col];
            val = acc;
        }
        g_W0c[l][t] = val;
    }
}

// ------------------------------------------------------------------ node_pre: node update (layer 0) + precompute(layer 1) + zero agg
// newh = h + elu([h,Hsum]·W0c + deg·v + b0)·W1 + b1
// PA = newh·WA1 + pos·Wp1 ; PB = newh·WB1 + eb0_1 − pos·Wp1  (fp16)
__global__ void node_pre_kernel(const float* __restrict__ W0c, const float* __restrict__ vv,
                                const float* __restrict__ W1, const float* __restrict__ b0,
                                const float* __restrict__ b1,
                                const float* __restrict__ E0, const float* __restrict__ eb0_1,
                                const float* __restrict__ pos, int Nn) {
    extern __shared__ float sm[];
    float* sW0 = sm;              // 8192 (combined, direct copy)
    float* sW1 = sm + 8192;       // 4096
    float* sWA = sm + 12288;      // 4096 (layer 1)
    float* sWB = sm + 16384;      // 4096
    float* sWp = sm + 20480;      // 192
    float* sv  = sm + 20672;      // 64
    float* snb0 = sm + 20736;     // 64
    float* snb1 = sm + 20800;     // 64
    float* seb0 = sm + 20864;     // 64
    float* stage = sm + 20928;    // 8 warps * 640

    for (int t = threadIdx.x; t < 8192; t += blockDim.x) sW0[t] = W0c[t];
    for (int t = threadIdx.x; t < 4096; t += blockDim.x) {
        int c = t & 3, lane_ = (t >> 2) & 31, kp = t >> 7;
        int k = 2 * kp + (c & 1);
        int col = lane_ + ((c & 2) ? 32 : 0);
        sW1[t] = W1[k * 64 + col];
        float wC = E0[(128 + k) * 64 + col];
        sWA[t] = E0[k * 64 + col] + wC;
        sWB[t] = E0[(64 + k) * 64 + col] - wC;
    }
    for (int t = threadIdx.x; t < 192; t += blockDim.x)
        sWp[t] = E0[(192 + (t >> 6)) * 64 + (t & 63)];
    if (threadIdx.x < 64) {
        sv[threadIdx.x]   = vv[threadIdx.x];
        snb0[threadIdx.x] = b0[threadIdx.x];
        snb1[threadIdx.x] = b1[threadIdx.x];
        seb0[threadIdx.x] = eb0_1[threadIdx.x];
    }
    __syncthreads();

    int lane = threadIdx.x & 31;
    int wid  = threadIdx.x >> 5;
    float* wbase = stage + wid * 640;
    float2* nP = reinterpret_cast<float2*>(wbase);
    const ulonglong2* W0v = reinterpret_cast<const ulonglong2*>(sW0);
    const ulonglong2* W1v = reinterpret_cast<const ulonglong2*>(sW1);
    const ulonglong2* WAv = reinterpret_cast<const ulonglong2*>(sWA);
    const ulonglong2* WBv = reinterpret_cast<const ulonglong2*>(sWB);
    const unsigned long long* nU = reinterpret_cast<const unsigned long long*>(nP);
    float* hF = wbase;

    int rL = ((lane >> 1) * 5) * 2 + (lane & 1);
    int rH = ((16 + (lane >> 1)) * 5) * 2 + (lane & 1);

    int wg = blockIdx.x * (blockDim.x >> 5) + wid;
    int ws = gridDim.x * (blockDim.x >> 5);
    for (int base = wg * 4; base < Nn; base += ws * 4) {
        float degf[4], p0v[4], p1v[4], p2v[4];
#pragma unroll
        for (int i = 0; i < 4; i++) {
            int n = base + i;
            if (n < Nn) {
                nP[lane * 5 + i]        = reinterpret_cast<const float2*>(g_h + n * 64)[lane];
                nP[(32 + lane) * 5 + i] = reinterpret_cast<const float2*>(g_agg + n * 64)[lane];
                degf[i] = (float)__ldg(&g_deg[n]);
                p0v[i] = __ldg(&pos[n * 3 + 0]);
                p1v[i] = __ldg(&pos[n * 3 + 1]);
                p2v[i] = __ldg(&pos[n * 3 + 2]);
                // zero agg for layer 1
                reinterpret_cast<float2*>(g_agg + n * 64)[lane] = make_float2(0.f, 0.f);
            } else {
                nP[lane * 5 + i]        = make_float2(0.f, 0.f);
                nP[(32 + lane) * 5 + i] = make_float2(0.f, 0.f);
                degf[i] = 0.f; p0v[i] = p1v[i] = p2v[i] = 0.f;
            }
        }
        __syncwarp();

        // hidden = elu([h, Hsum]·W0c + deg·v + b0)
        unsigned long long c0[4] = {0,0,0,0}, c1[4] = {0,0,0,0};
#pragma unroll 4
        for (int kp = 0; kp < 64; kp++) {
            ulonglong2 w = W0v[kp * 32 + lane];
#pragma unroll
            for (int i = 0; i < 4; i++) {
                unsigned long long v = nU[kp * 5 + i];
                ffma2(c0[i], v, w.x); ffma2(c1[i], v, w.y);
            }
        }
        float b0a = snb0[lane], b0b = snb0[lane + 32];
        float svL = sv[lane],   svH = sv[lane + 32];
        float hL[4], hH[4];
#pragma unroll
        for (int i = 0; i < 4; i++) {
            hL[i] = elu_f(usum(c0[i]) + degf[i] * svL + b0a);
            hH[i] = elu_f(usum(c1[i]) + degf[i] * svH + b0b);
        }
        __syncwarp();
#pragma unroll
        for (int i = 0; i < 4; i++) {
            hF[rL + 2 * i] = hL[i];
            hF[rH + 2 * i] = hH[i];
        }
        __syncwarp();

        // u = hidden·W1 + b1 ; newh = oldh + u
        unsigned long long d0[4] = {0,0,0,0}, d1[4] = {0,0,0,0};
#pragma unroll 4
        for (int kp = 0; kp < 32; kp++) {
            ulonglong2 w = W1v[kp * 32 + lane];
#pragma unroll
            for (int i = 0; i < 4; i++) {
                unsigned long long v = nU[kp * 5 + i];
                ffma2(d0[i], v, w.x); ffma2(d1[i], v, w.y);
            }
        }
        float b1a = snb1[lane], b1b = snb1[lane + 32];
        float nhL[4], nhH[4];
#pragma unroll
        for (int i = 0; i < 4; i++) {
            int n = base + i;
            if (n < Nn) {
                nhL[i] = g_h[n * 64 + lane]      + usum(d0[i]) + b1a;
                nhH[i] = g_h[n * 64 + 32 + lane] + usum(d1[i]) + b1b;
                g_h[n * 64 + lane]      = nhL[i];
                g_h[n * 64 + 32 + lane] = nhH[i];
            } else { nhL[i] = 0.f; nhH[i] = 0.f; }
        }
        __syncwarp();
#pragma unroll
        for (int i = 0; i < 4; i++) {
            hF[rL + 2 * i] = nhL[i];
            hF[rH + 2 * i] = nhH[i];
        }
        __syncwarp();

        // PA/PB for layer 1
        unsigned long long aA0[4] = {0,0,0,0}, aA1[4] = {0,0,0,0};
        unsigned long long aB0[4] = {0,0,0,0}, aB1[4] = {0,0,0,0};
#pragma unroll 4
        for (int kp = 0; kp < 32; kp++) {
            ulonglong2 wa = WAv[kp * 32 + lane];
            ulonglong2 wb = WBv[kp * 32 + lane];
#pragma unroll
            for (int i = 0; i < 4; i++) {
                unsigned long long v = nU[kp * 5 + i];
                ffma2(aA0[i], v, wa.x); ffma2(aA1[i], v, wa.y);
                ffma2(aB0[i], v, wb.x); ffma2(aB1[i], v, wb.y);
            }
        }
        float eb0a = seb0[lane], eb0b = seb0[lane + 32];
        float wpL0 = sWp[lane], wpL1 = sWp[64 + lane], wpL2 = sWp[128 + lane];
        float wpH0 = sWp[lane + 32], wpH1 = sWp[64 + lane + 32], wpH2 = sWp[128 + lane + 32];
#pragma unroll
        for (int i = 0; i < 4; i++) {
            int n = base + i;
            if (n < Nn) {
                float wpa = p0v[i] * wpL0 + p1v[i] * wpL1 + p2v[i] * wpL2;
                float wpb = p0v[i] * wpH0 + p1v[i] * wpH1 + p2v[i] * wpH2;
                g_PAh[n * 64 + lane]      = __float2half(usum(aA0[i]) + wpa);
                g_PAh[n * 64 + 32 + lane] = __float2half(usum(aA1[i]) + wpb);
                g_PBh[n * 64 + lane]      = __float2half(usum(aB0[i]) + eb0a - wpa);
                g_PBh[n * 64 + 32 + lane] = __float2half(usum(aB1[i]) + eb0b - wpb);
            }
        }
        __syncwarp();
    }
}

// ------------------------------------------------------------------ node_dec: node update (layer 1) + decoder (h never written)
__global__ void node_dec_kernel(const float* __restrict__ W0c, const float* __restrict__ vv,
                                const float* __restrict__ W1, const float* __restrict__ b0,
                                const float* __restrict__ b1,
                                const float* __restrict__ dW0, const float* __restrict__ db0,
                                const float* __restrict__ dW1, const float* __restrict__ db1,
                                float* __restrict__ out, int Nn) {
    extern __shared__ float sm[];
    float* sW0 = sm;              // 8192
    float* sW1 = sm + 8192;       // 4096
    float* sdW0 = sm + 12288;     // 4096
    float* sdW1 = sm + 16384;     // 192
    float* sv  = sm + 16576;      // 64
    float* snb0 = sm + 16640;     // 64
    float* snb1 = sm + 16704;     // 64
    float* sdb0 = sm + 16768;     // 64
    float* sdb1 = sm + 16832;     // 4
    float* stage = sm + 16836;    // 8 warps * 640

    for (int t = threadIdx.x; t < 8192; t += blockDim.x) sW0[t] = W0c[t];
    for (int t = threadIdx.x; t < 4096; t += blockDim.x) {
        int c = t & 3, lane_ = (t >> 2) & 31, kp = t >> 7;
        int k = 2 * kp + (c & 1);
        int col = lane_ + ((c & 2) ? 32 : 0);
        sW1[t] = W1[k * 64 + col];
        sdW0[t] = dW0[k * 64 + col];
    }
    for (int t = threadIdx.x; t < 192; t += blockDim.x) sdW1[t] = dW1[t];
    if (threadIdx.x < 64) {
        sv[threadIdx.x]   = vv[threadIdx.x];
        snb0[threadIdx.x] = b0[threadIdx.x];
        snb1[threadIdx.x] = b1[threadIdx.x];
        sdb0[threadIdx.x] = db0[threadIdx.x];
    }
    if (threadIdx.x < 3) sdb1[threadIdx.x] = db1[threadIdx.x];
    __syncthreads();

    int lane = threadIdx.x & 31;
    int wid  = threadIdx.x >> 5;
    float* wbase = stage + wid * 640;
    float2* nP = reinterpret_cast<float2*>(wbase);
    const ulonglong2* W0v = reinterpret_cast<const ulonglong2*>(sW0);
    const ulonglong2* W1v = reinterpret_cast<const ulonglong2*>(sW1);
    const ulonglong2* dW0v = reinterpret_cast<const ulonglong2*>(sdW0);
    const unsigned long long* nU = reinterpret_cast<const unsigned long long*>(nP);
    float* hF = wbase;

    int rL = ((lane >> 1) * 5) * 2 + (lane & 1);
    int rH = ((16 + (lane >> 1)) * 5) * 2 + (lane & 1);

    int wg = blockIdx.x * (blockDim.x >> 5) + wid;
    int ws = gridDim.x * (blockDim.x >> 5);
    for (int base = wg * 4; base < Nn; base += ws * 4) {
        float degf[4];
#pragma unroll
        for (int i = 0; i < 4; i++) {
            int n = base + i;
            if (n < Nn) {
                nP[lane * 5 + i]        = reinterpret_cast<const float2*>(g_h + n * 64)[lane];
                nP[(32 + lane) * 5 + i] = reinterpret_cast<const float2*>(g_agg + n * 64)[lane];
                degf[i] = (float)__ldg(&g_deg[n]);
            } else {
                nP[lane * 5 + i]        = make_float2(0.f, 0.f);
                nP[(32 + lane) * 5 + i] = make_float2(0.f, 0.f);
                degf[i] = 0.f;
            }
        }
        __syncwarp();

        // hidden = elu([h, Hsum]·W0c + deg·v + b0)
        unsigned long long c0[4] = {0,0,0,0}, c1[4] = {0,0,0,0};
#pragma unroll 4
        for (int kp = 0; kp < 64; kp++) {
            ulonglong2 w = W0v[kp * 32 + lane];
#pragma unroll
            for (int i = 0; i < 4; i++) {
                unsigned long long v = nU[kp * 5 + i];
                ffma2(c0[i], v, w.x); ffma2(c1[i], v, w.y);
            }
        }
        float b0a = snb0[lane], b0b = snb0[lane + 32];
        float svL = sv[lane],   svH = sv[lane + 32];
        float hL[4], hH[4];
#pragma unroll
        for (int i = 0; i < 4; i++) {
            hL[i] = elu_f(usum(c0[i]) + degf[i] * svL + b0a);
            hH[i] = elu_f(usum(c1[i]) + degf[i] * svH + b0b);
        }
        __syncwarp();
#pragma unroll
        for (int i = 0; i < 4; i++) {
            hF[rL + 2 * i] = hL[i];
            hF[rH + 2 * i] = hH[i];
        }
        __syncwarp();

        // u = hidden·W1 + b1 ; newh = oldh + u (registers only)
        unsigned long long d0[4] = {0,0,0,0}, d1[4] = {0,0,0,0};
#pragma unroll 4
        for (int kp = 0; kp < 32; kp++) {
            ulonglong2 w = W1v[kp * 32 + lane];
#pragma unroll
            for (int i = 0; i < 4; i++) {
                unsigned long long v = nU[kp * 5 + i];
                ffma2(d0[i], v, w.x); ffma2(d1[i], v, w.y);
            }
        }
        float b1a = snb1[lane], b1b = snb1[lane + 32];
        float nhL[4], nhH[4];
#pragma unroll
        for (int i = 0; i < 4; i++) {
            int n = base + i;
            if (n < Nn) {
                nhL[i] = g_h[n * 64 + lane]      + usum(d0[i]) + b1a;
                nhH[i] = g_h[n * 64 + 32 + lane] + usum(d1[i]) + b1b;
            } else { nhL[i] = 0.f; nhH[i] = 0.f; }
        }
        __syncwarp();
#pragma unroll
        for (int i = 0; i < 4; i++) {
            hF[rL + 2 * i] = nhL[i];
            hF[rH + 2 * i] = nhH[i];
        }
        __syncwarp();

        // decoder: hidden = elu(newh·dW0 + db0) ; out = hidden·dW1 + db1
        unsigned long long e0[4] = {0,0,0,0}, e1[4] = {0,0,0,0};
#pragma unroll 4
        for (int kp = 0; kp < 32; kp++) {
            ulonglong2 w = dW0v[kp * 32 + lane];
#pragma unroll
            for (int i = 0; i < 4; i++) {
                unsigned long long v = nU[kp * 5 + i];
                ffma2(e0[i], v, w.x); ffma2(e1[i], v, w.y);
            }
        }
        float db0a = sdb0[lane], db0b = sdb0[lane + 32];
        float w1L0 = sdW1[lane * 3 + 0], w1L1 = sdW1[lane * 3 + 1], w1L2 = sdW1[lane * 3 + 2];
        float w1H0 = sdW1[(lane + 32) * 3 + 0], w1H1 = sdW1[(lane + 32) * 3 + 1], w1H2 = sdW1[(lane + 32) * 3 + 2];
#pragma unroll
        for (int i = 0; i < 4; i++) {
            int n = base + i;
            float hid0 = elu_f(usum(e0[i]) + db0a);
            float hid1 = elu_f(usum(e1[i]) + db0b);
            float p0 = hid0 * w1L0 + hid1 * w1H0;
            float p1 = hid0 * w1L1 + hid1 * w1H1;
            float p2 = hid0 * w1L2 + hid1 * w1H2;
#pragma unroll
            for (int off = 16; off; off >>= 1) {
                p0 += __shfl_xor_sync(~0u, p0, off);
                p1 += __shfl_xor_sync(~0u, p1, off);
                p2 += __shfl_xor_sync(~0u, p2, off);
            }
            if (lane == 0 && n < Nn) {
                out[n * 3 + 0] = p0 + sdb1[0];
                out[n * 3 + 1] = p1 + sdb1[1];
                out[n * 3 + 2] = p2 + sdb1[2];
            }
        }
        __syncwarp();
    }
}

// ------------------------------------------------------------------ launch
extern "C" void kernel_launch(void* const* d_in, const int* in_sizes, int n_in,
                              void* d_out, int out_size) {
    const float* x      = (const float*)d_in[0];
    const float* pos    = (const float*)d_in[1];
    const int*   ei     = (const int*)d_in[2];
    const float* enc_W0 = (const float*)d_in[3];
    const float* enc_b0 = (const float*)d_in[4];
    const float* enc_W1 = (const float*)d_in[5];
    const float* enc_b1 = (const float*)d_in[6];
    const float* dec_W0 = (const float*)d_in[7];
    const float* dec_b0 = (const float*)d_in[8];
    const float* dec_W1 = (const float*)d_in[9];
    const float* dec_b1 = (const float*)d_in[10];
    const float* eW0    = (const float*)d_in[11];
    const float* eb0    = (const float*)d_in[12];
    const float* eW1    = (const float*)d_in[13];
    const float* eb1    = (const float*)d_in[14];
    const float* nW0    = (const float*)d_in[15];
    const float* nb0    = (const float*)d_in[16];
    const float* nW1    = (const float*)d_in[17];
    const float* nb1    = (const float*)d_in[18];

    int Nn   = in_sizes[0] / 3;
    int Ecnt = in_sizes[2] / 2;
    if (Ecnt > EMAX) Ecnt = EMAX;
    float* out = (float*)d_out;

    const int ENCP_SMEM = (12864 + 8 * 320) * 4;   // 61,696 B
    const int NPRE_SMEM = (20928 + 8 * 640) * 4;   // 104,192 B
    const int NDEC_SMEM = (16836 + 8 * 640) * 4;   // 87,824 B
    cudaFuncSetAttribute(enc_pre_kernel,  cudaFuncAttributeMaxDynamicSharedMemorySize, ENCP_SMEM);
    cudaFuncSetAttribute(node_pre_kernel, cudaFuncAttributeMaxDynamicSharedMemorySize, NPRE_SMEM);
    cudaFuncSetAttribute(node_dec_kernel, cudaFuncAttributeMaxDynamicSharedMemorySize, NDEC_SMEM);

    const int TPB = 256;
    const float* E0_0 = eW0;
    const float* E0_1 = eW0 + (size_t)195 * 64;

    float* w0c; float* vv;
    cudaGetSymbolAddress((void**)&w0c, g_W0c);
    cudaGetSymbolAddress((void**)&vv,  g_v);

    probe_zero_kernel<<<148, TPB>>>(ei, Nn);                                          // 0
    convert_kernel<<<444, TPB>>>(ei, Ecnt, Nn);                                       // 1
    enc_pre_kernel<<<296, TPB, ENCP_SMEM>>>(x, pos, enc_W0, enc_b0, enc_W1, enc_b1,
                                            E0_0, eb0, Nn);                           // 2
    edge_scatter_kernel<<<888, TPB>>>(Ecnt);                                          // 3  ← profiled
    prep_kernel<<<2, 256>>>(eW1, eb1, nW0);                                           // 4
    node_pre_kernel<<<296, TPB, NPRE_SMEM>>>(w0c, vv, nW1, nb0, nb1,
                                             E0_1, eb0 + 64, pos, Nn);                // 5
    edge_scatter_kernel<<<888, TPB>>>(Ecnt);                                          // 6
    node_dec_kernel<<<296, TPB, NDEC_SMEM>>>(w0c + 8192, vv + 64,
                                             nW1 + (size_t)64 * 64, nb0 + 64, nb1 + 64,
                                             dec_W0, dec_b0, dec_W1, dec_b1, out, Nn); // 7
}